// round 2
// baseline (speedup 1.0000x reference)
#include <cuda_runtime.h>
#include <math.h>

#define BB 16
#define CC 256
#define HH 128
#define WW 128
#define HW 16384
#define MM 32
#define NMODE 1024
#define TD 512
#define CD 512
#define NG 8
#define EPSV 1e-5f

// ---------------- persistent scratch ----------------
__device__ float2 g_A[(size_t)BB*CC*HH*MM];   // fwd-ky result A[b,c,n,ky]; reused as G[b,o,n,ky] after kD
__device__ float2 g_Smode[(size_t)BB*CC*NMODE]; // S[b,c,kx*32+ky]
__device__ float2 g_Omode[(size_t)BB*CC*NMODE]; // mixed modes
__device__ float  g_h[(size_t)BB*CC*HW];        // spectral irfft, then pre-GN activation
__device__ float  g_tvec[BB*CC];
__device__ float  g_scale[BB*CC];
__device__ float  g_shift[BB*CC];
__device__ float  g_stats[BB*NG*2];
__device__ float2 g_tabJK[HH*MM];  // [j][k] = (cos,sin)(2*pi*j*k/128)
__device__ float2 g_tabKJ[MM*HH];  // [k][j]

// ---------------- K0: tables + embedding projections + zero stats ----------------
__global__ void k0_prep(const float* __restrict__ t_emb, const float* __restrict__ cond_emb,
                        const float* __restrict__ tp_w, const float* __restrict__ tp_b,
                        const float* __restrict__ cp_w, const float* __restrict__ cp_b) {
    int t = threadIdx.x;
    if (blockIdx.x == BB) {
        for (int e = t; e < HH*MM; e += 256) {
            int j = e >> 5, k = e & 31;
            float ang = (float)((j * k) & 127) * 0.049087385212340517f; // 2*pi/128
            float s, c; sincosf(ang, &s, &c);
            g_tabJK[j*MM + k] = make_float2(c, s);
            g_tabKJ[k*HH + j] = make_float2(c, s);
        }
        if (t < BB*NG*2) g_stats[t] = 0.f;
        return;
    }
    int b = blockIdx.x;
    __shared__ float st[TD];
    __shared__ float sc[CD];
    for (int e = t; e < TD; e += 256) { float v = t_emb[b*TD + e];   st[e] = v / (1.f + expf(-v)); }
    for (int e = t; e < CD; e += 256) { float v = cond_emb[b*CD + e]; sc[e] = v / (1.f + expf(-v)); }
    __syncthreads();
    int c = t;  // 256 threads == 256 channels
    float tv = tp_b[c], s1 = cp_b[c], s2 = cp_b[c + CC];
    const float* tw = tp_w + (size_t)c*TD;
    const float* c1 = cp_w + (size_t)c*CD;
    const float* c2 = cp_w + (size_t)(c + CC)*CD;
    for (int d = 0; d < TD; d++) tv = fmaf(st[d], tw[d], tv);
    for (int d = 0; d < CD; d++) { s1 = fmaf(sc[d], c1[d], s1); s2 = fmaf(sc[d], c2[d], s2); }
    g_tvec[b*CC + c] = tv;
    g_scale[b*CC + c] = s1;
    g_shift[b*CC + c] = s2;
}

// ---------------- kA: forward DFT along w (m -> ky), per row ----------------
__global__ void __launch_bounds__(256) kA_fwd_ky(const float* __restrict__ x) {
    __shared__ float xs[32][WW + 1];
    int t = threadIdx.x;
    int R0 = blockIdx.x * 32;   // row index into [B*C*H, W]
    for (int q = 0; q < 16; q++) {
        int idx = t + 256*q;
        xs[idx >> 7][idx & 127] = x[(size_t)R0*WW + idx];
    }
    __syncthreads();
    int ky2 = t & 15, rp = t >> 4;
    int r0 = rp * 2;
    float ar[2][2] = {{0.f,0.f},{0.f,0.f}}, ai[2][2] = {{0.f,0.f},{0.f,0.f}};
    for (int m = 0; m < WW; m++) {
        float x0 = xs[r0][m], x1 = xs[r0 + 1][m];
        #pragma unroll
        for (int ks = 0; ks < 2; ks++) {
            float2 cs = g_tabJK[m*MM + ky2 + 16*ks];   // e^{-i theta} = c - i s
            ar[0][ks] = fmaf(x0, cs.x, ar[0][ks]);
            ai[0][ks] = fmaf(-x0, cs.y, ai[0][ks]);
            ar[1][ks] = fmaf(x1, cs.x, ar[1][ks]);
            ai[1][ks] = fmaf(-x1, cs.y, ai[1][ks]);
        }
    }
    #pragma unroll
    for (int rr = 0; rr < 2; rr++)
        #pragma unroll
        for (int ks = 0; ks < 2; ks++)
            g_A[(size_t)(R0 + r0 + rr)*MM + ky2 + 16*ks] = make_float2(ar[rr][ks], ai[rr][ks]);
}

// ---------------- kB: forward DFT along h (n -> kx), complex ----------------
__global__ void __launch_bounds__(256) kB_fwd_kx() {
    __shared__ float2 sA[HH][MM];  // 32KB
    int t = threadIdx.x;
    int bc = blockIdx.x;           // (b*256 + c)
    const float2* Ap = g_A + (size_t)bc*HH*MM;
    for (int q = 0; q < 16; q++) ((float2*)sA)[t + 256*q] = Ap[t + 256*q];
    __syncthreads();
    int ky = t & 31, kxb = t >> 5;
    float sr[4] = {0,0,0,0}, si[4] = {0,0,0,0};
    for (int n = 0; n < HH; n++) {
        float2 a = sA[n][ky];
        #pragma unroll
        for (int j = 0; j < 4; j++) {
            float2 cs = g_tabJK[n*MM + kxb + 8*j];
            // (Ar + iAi)(c - i s): re = Ar c + Ai s, im = Ai c - Ar s
            sr[j] = fmaf(a.x, cs.x, sr[j]); sr[j] = fmaf(a.y, cs.y, sr[j]);
            si[j] = fmaf(a.y, cs.x, si[j]); si[j] = fmaf(-a.x, cs.y, si[j]);
        }
    }
    const float scl = 1.f/128.f;  // forward ortho
    #pragma unroll
    for (int j = 0; j < 4; j++) {
        int kx = kxb + 8*j;
        g_Smode[(size_t)bc*NMODE + kx*MM + ky] = make_float2(sr[j]*scl, si[j]*scl);
    }
}

// ---------------- kC: per-mode complex channel mix ----------------
__global__ void __launch_bounds__(256) kC_mix(const float* __restrict__ w_real,
                                              const float* __restrict__ w_imag) {
    __shared__ float2 sS[BB][MM];    // 4KB
    __shared__ float  sW[2][8][MM];  // 2KB
    int t = threadIdx.x;
    int kx = blockIdx.x >> 5;
    int o0 = (blockIdx.x & 31) * 8;
    int ky = t & 31, bq = t >> 5;
    float orr[2][8] = {}, oii[2][8] = {};
    for (int i = 0; i < CC; i++) {
        {   // load S[b][i][kx*32 + 0..31] for all 16 b: 256 float4
            int bb = t >> 4, f = t & 15;
            const float4* src = (const float4*)g_Smode;
            ((float4*)sS)[t] = src[((((size_t)(bb*CC + i)) << 10) + ((size_t)kx << 5) >> 1) + f];
        }
        if (t < 128) {  // load wr/wi[i][o0..o0+7][kx][0..31]
            int half = t >> 6, tt = t & 63, o = tt >> 3, f = tt & 7;
            const float* src = half ? w_imag : w_real;
            const float4* s4 = (const float4*)(src + (((size_t)(i*CC + o0 + o)) << 10) + (kx << 5));
            ((float4*)&sW[half][o][0])[f] = s4[f];
        }
        __syncthreads();
        #pragma unroll
        for (int b2 = 0; b2 < 2; b2++) {
            float2 s = sS[bq + 8*b2][ky];
            #pragma unroll
            for (int o = 0; o < 8; o++) {
                float wr = sW[0][o][ky], wi = sW[1][o][ky];
                orr[b2][o] = fmaf(s.x, wr, orr[b2][o]);
                orr[b2][o] = fmaf(-s.y, wi, orr[b2][o]);
                oii[b2][o] = fmaf(s.x, wi, oii[b2][o]);
                oii[b2][o] = fmaf(s.y, wr, oii[b2][o]);
            }
        }
        __syncthreads();
    }
    #pragma unroll
    for (int b2 = 0; b2 < 2; b2++) {
        int b = bq + 8*b2;
        #pragma unroll
        for (int o = 0; o < 8; o++)
            g_Omode[(((size_t)(b*CC + o0 + o)) << 10) + (kx << 5) + ky] =
                make_float2(orr[b2][o], oii[b2][o]);
    }
}

// ---------------- kD: inverse DFT along kx (kx -> n), complex; fold c_ky/128 ----------------
__global__ void __launch_bounds__(256) kD_inv_kx() {
    __shared__ float2 sO[MM][MM];  // 8KB
    int t = threadIdx.x;
    int bo = blockIdx.x;           // (b*256 + o)
    const float2* Op = g_Omode + (size_t)bo*NMODE;
    for (int q = 0; q < 4; q++) ((float2*)sO)[t + 256*q] = Op[t + 256*q];
    __syncthreads();
    int ky = t & 31, nq = t >> 5;
    float gr[16], gi[16];
    #pragma unroll
    for (int q = 0; q < 16; q++) { gr[q] = 0.f; gi[q] = 0.f; }
    for (int kx = 0; kx < MM; kx++) {
        float2 o = sO[kx][ky];
        #pragma unroll
        for (int q = 0; q < 16; q++) {
            int n = nq*16 + q;
            float2 cs = g_tabJK[n*MM + kx];   // e^{+i theta}
            gr[q] = fmaf(o.x, cs.x, gr[q]); gr[q] = fmaf(-o.y, cs.y, gr[q]);
            gi[q] = fmaf(o.x, cs.y, gi[q]); gi[q] = fmaf(o.y, cs.x, gi[q]);
        }
    }
    float fac = (ky == 0 ? 1.f : 2.f) * (1.f/128.f);  // C2R doubling + inverse ortho
    #pragma unroll
    for (int q = 0; q < 16; q++) {
        int n = nq*16 + q;
        g_A[(size_t)bo*HH*MM + n*MM + ky] = make_float2(gr[q]*fac, gi[q]*fac);
    }
}

// ---------------- kE: inverse C2R along ky (ky -> m); writes spectral part to g_h ----------------
__global__ void __launch_bounds__(256) kE_inv_m() {
    __shared__ float2 sG[64][MM];  // 16KB
    int t = threadIdx.x;
    int bo = blockIdx.x >> 1, nh = blockIdx.x & 1;
    const float2* Gp = g_A + (size_t)bo*HH*MM + (size_t)nh*64*MM;
    for (int q = 0; q < 8; q++) ((float2*)sG)[t + 256*q] = Gp[t + 256*q];
    __syncthreads();
    int m = t & 127, nq2 = t >> 7;
    float acc[32];
    #pragma unroll
    for (int i = 0; i < 32; i++) acc[i] = 0.f;
    for (int kc = 0; kc < 4; kc++) {
        float tc[8], ts[8];
        #pragma unroll
        for (int j = 0; j < 8; j++) {
            float2 cs = g_tabKJ[(kc*8 + j)*HH + m];
            tc[j] = cs.x; ts[j] = cs.y;
        }
        #pragma unroll
        for (int i = 0; i < 32; i++) {
            int nl = nq2*32 + i;
            #pragma unroll
            for (int j = 0; j < 8; j++) {
                float2 g = sG[nl][kc*8 + j];
                acc[i] = fmaf(g.x, tc[j], acc[i]);
                acc[i] = fmaf(-g.y, ts[j], acc[i]);
            }
        }
    }
    float* outp = g_h + (size_t)bo*HW + (size_t)(nh*64)*WW;
    #pragma unroll
    for (int i = 0; i < 32; i++)
        outp[(nq2*32 + i)*WW + m] = acc[i];
}

// ---------------- kF: pointwise GEMM + bias + t-proj + FiLM + GN stats ----------------
__global__ void __launch_bounds__(256) kF_pointwise(const float* __restrict__ x,
                                                    const float* __restrict__ pw_w,
                                                    const float* __restrict__ pw_b) {
    __shared__ float xs[16][128];
    __shared__ float ws[64][17];
    int t = threadIdx.x;
    int b = blockIdx.x >> 9, rem = blockIdx.x & 511;
    int o0 = (rem >> 7) * 64, hw0 = (rem & 127) * 128;
    int hwq = t & 31, oq = t >> 5;
    float acc[8][4] = {};
    for (int i0 = 0; i0 < CC; i0 += 16) {
        for (int q = 0; q < 8; q++) {
            int idx = t + 256*q;
            xs[idx >> 7][idx & 127] =
                x[(((size_t)(b*CC + i0 + (idx >> 7))) << 14) + hw0 + (idx & 127)];
        }
        for (int q = 0; q < 4; q++) {
            int idx = t + 256*q;
            ws[idx >> 4][idx & 15] = pw_w[(size_t)(o0 + (idx >> 4))*CC + i0 + (idx & 15)];
        }
        __syncthreads();
        #pragma unroll
        for (int k = 0; k < 16; k++) {
            float4 xv = *(const float4*)&xs[k][hwq*4];
            #pragma unroll
            for (int j = 0; j < 8; j++) {
                float w = ws[oq*8 + j][k];
                acc[j][0] = fmaf(xv.x, w, acc[j][0]);
                acc[j][1] = fmaf(xv.y, w, acc[j][1]);
                acc[j][2] = fmaf(xv.z, w, acc[j][2]);
                acc[j][3] = fmaf(xv.w, w, acc[j][3]);
            }
        }
        __syncthreads();
    }
    float lsum = 0.f, lsum2 = 0.f;
    #pragma unroll
    for (int j = 0; j < 8; j++) {
        int o = o0 + oq*8 + j;
        float addb = pw_b[o] + g_tvec[b*CC + o];
        float scl = 1.f + g_scale[b*CC + o];
        float shf = g_shift[b*CC + o];
        size_t idx = (((size_t)(b*CC + o)) << 14) + hw0 + hwq*4;
        float4 hv = *(float4*)&g_h[idx];
        float v0 = (acc[j][0] + hv.x + addb)*scl + shf;
        float v1 = (acc[j][1] + hv.y + addb)*scl + shf;
        float v2 = (acc[j][2] + hv.z + addb)*scl + shf;
        float v3 = (acc[j][3] + hv.w + addb)*scl + shf;
        *(float4*)&g_h[idx] = make_float4(v0, v1, v2, v3);
        lsum  += v0 + v1 + v2 + v3;
        lsum2 += v0*v0 + v1*v1 + v2*v2 + v3*v3;
    }
    for (int off = 16; off; off >>= 1) {
        lsum  += __shfl_xor_sync(0xffffffffu, lsum, off);
        lsum2 += __shfl_xor_sync(0xffffffffu, lsum2, off);
    }
    if ((t & 31) == 0) {
        int g = (o0 + oq*8) >> 5;
        atomicAdd(&g_stats[(b*NG + g)*2],     lsum);
        atomicAdd(&g_stats[(b*NG + g)*2 + 1], lsum2);
    }
}

// ---------------- kG: finalize GroupNorm stats ----------------
__global__ void kG_stats() {
    int t = threadIdx.x;
    if (t < BB*NG) {
        float s = g_stats[t*2], s2 = g_stats[t*2 + 1];
        const float inv = 1.f / 524288.f;  // 32 * 128 * 128
        float mu = s * inv;
        float var = s2 * inv - mu*mu;
        g_stats[t*2]     = mu;
        g_stats[t*2 + 1] = rsqrtf(var + EPSV);
    }
}

// ---------------- kH: normalize + affine + GELU + residual ----------------
__device__ __forceinline__ float gelu_res(float h, float xr, float ga, float be) {
    float hn = fmaf(h, ga, be);
    return xr + 0.5f*hn*(1.f + erff(hn*0.70710678118654752f));
}

__global__ void __launch_bounds__(256) kH_final(const float* __restrict__ x,
                                                const float* __restrict__ gn_g,
                                                const float* __restrict__ gn_b,
                                                float* __restrict__ out) {
    int idx4 = blockIdx.x*256 + threadIdx.x;
    int base = idx4 << 2;
    int c = (base >> 14) & 255;
    int b = base >> 22;
    int g = c >> 5;
    float mu = g_stats[(b*NG + g)*2];
    float rs = g_stats[(b*NG + g)*2 + 1];
    float ga = gn_g[c] * rs;
    float be = gn_b[c] - mu * ga;   // hn = (h-mu)*rs*gn_g + gn_b == h*ga + be
    float4 hv = ((const float4*)g_h)[idx4];
    float4 xv = ((const float4*)x)[idx4];
    float4 r;
    r.x = gelu_res(hv.x, xv.x, ga, be);
    r.y = gelu_res(hv.y, xv.y, ga, be);
    r.z = gelu_res(hv.z, xv.z, ga, be);
    r.w = gelu_res(hv.w, xv.w, ga, be);
    ((float4*)out)[idx4] = r;
}

extern "C" void kernel_launch(void* const* d_in, const int* in_sizes, int n_in,
                              void* d_out, int out_size) {
    const float* x        = (const float*)d_in[0];
    const float* t_emb    = (const float*)d_in[1];
    const float* cond_emb = (const float*)d_in[2];
    const float* w_real   = (const float*)d_in[3];
    const float* w_imag   = (const float*)d_in[4];
    const float* pw_w     = (const float*)d_in[5];
    const float* pw_b     = (const float*)d_in[6];
    const float* tp_w     = (const float*)d_in[7];
    const float* tp_b     = (const float*)d_in[8];
    const float* cp_w     = (const float*)d_in[9];
    const float* cp_b     = (const float*)d_in[10];
    const float* gn_g     = (const float*)d_in[11];
    const float* gn_b     = (const float*)d_in[12];
    float* out = (float*)d_out;

    k0_prep<<<BB + 1, 256>>>(t_emb, cond_emb, tp_w, tp_b, cp_w, cp_b);
    kA_fwd_ky<<<16384, 256>>>(x);     // 524288 rows / 32
    kB_fwd_kx<<<4096, 256>>>();       // B*C
    kC_mix<<<1024, 256>>>(w_real, w_imag);  // 32 kx * 32 o-tiles
    kD_inv_kx<<<4096, 256>>>();       // B*C
    kE_inv_m<<<8192, 256>>>();        // B*C * 2
    kF_pointwise<<<8192, 256>>>(x, pw_w, pw_b); // 16 b * 4 o-tiles * 128 hw-tiles
    kG_stats<<<1, 256>>>();
    kH_final<<<65536, 256>>>(x, gn_g, gn_b, out);
}

// round 4
// speedup vs baseline: 1.3927x; 1.3927x over previous
#include <cuda_runtime.h>
#include <cstdint>
#include <math.h>

#define BB 16
#define CC 256
#define HH 128
#define WW 128
#define HW 16384
#define MM 32
#define NMODE 1024
#define TD 512
#define CD 512
#define NG 8
#define EPSV 1e-5f

// ---------------- persistent scratch ----------------
__device__ float2 g_A[(size_t)BB*CC*HH*MM];
__device__ float2 g_Smode[(size_t)BB*CC*NMODE];
__device__ float2 g_Omode[(size_t)BB*CC*NMODE];
__device__ float  g_h[(size_t)BB*CC*HW];
__device__ float  g_tvec[BB*CC];
__device__ float  g_scale[BB*CC];
__device__ float  g_shift[BB*CC];
__device__ float  g_stats[BB*NG*2];
__device__ float2 g_tabJK[HH*MM];
__device__ float2 g_tabKJ[MM*HH];

// ---------------- helpers ----------------
__device__ __forceinline__ uint32_t smem_u32(const void* p) {
    return (uint32_t)__cvta_generic_to_shared(p);
}
__device__ __forceinline__ void cpasync16(uint32_t dst, const void* src) {
    asm volatile("cp.async.ca.shared.global [%0], [%1], 16;" :: "r"(dst), "l"(src));
}
__device__ __forceinline__ void cpcommit() { asm volatile("cp.async.commit_group;"); }
template<int N>
__device__ __forceinline__ void cpwait() { asm volatile("cp.async.wait_group %0;" :: "n"(N)); }
__device__ __forceinline__ uint32_t f2tf(float v) {
    uint32_t r;
    asm("cvt.rna.tf32.f32 %0, %1;" : "=r"(r) : "f"(v));
    return r;
}
__device__ __forceinline__ void mma_tf32(float* d, const uint32_t* a, const uint32_t* b) {
    asm volatile("mma.sync.aligned.m16n8k8.row.col.f32.tf32.tf32.f32 "
                 "{%0,%1,%2,%3}, {%4,%5,%6,%7}, {%8,%9}, {%0,%1,%2,%3};"
                 : "+f"(d[0]), "+f"(d[1]), "+f"(d[2]), "+f"(d[3])
                 : "r"(a[0]), "r"(a[1]), "r"(a[2]), "r"(a[3]), "r"(b[0]), "r"(b[1]));
}

// ---------------- K0: tables + embedding projections + zero stats ----------------
__global__ void k0_prep(const float* __restrict__ t_emb, const float* __restrict__ cond_emb,
                        const float* __restrict__ tp_w, const float* __restrict__ tp_b,
                        const float* __restrict__ cp_w, const float* __restrict__ cp_b) {
    int t = threadIdx.x;
    if (blockIdx.x == BB) {
        for (int e = t; e < HH*MM; e += 256) {
            int j = e >> 5, k = e & 31;
            float ang = (float)((j * k) & 127) * 0.049087385212340517f;
            float s, c; sincosf(ang, &s, &c);
            g_tabJK[j*MM + k] = make_float2(c, s);
            g_tabKJ[k*HH + j] = make_float2(c, s);
        }
        if (t < BB*NG*2) g_stats[t] = 0.f;
        return;
    }
    int b = blockIdx.x;
    __shared__ float st[TD];
    __shared__ float sc[CD];
    for (int e = t; e < TD; e += 256) { float v = t_emb[b*TD + e];   st[e] = v / (1.f + expf(-v)); }
    for (int e = t; e < CD; e += 256) { float v = cond_emb[b*CD + e]; sc[e] = v / (1.f + expf(-v)); }
    __syncthreads();
    int c = t;
    float tv = tp_b[c], s1 = cp_b[c], s2 = cp_b[c + CC];
    const float* tw = tp_w + (size_t)c*TD;
    const float* c1 = cp_w + (size_t)c*CD;
    const float* c2 = cp_w + (size_t)(c + CC)*CD;
    for (int d = 0; d < TD; d++) tv = fmaf(st[d], tw[d], tv);
    for (int d = 0; d < CD; d++) { s1 = fmaf(sc[d], c1[d], s1); s2 = fmaf(sc[d], c2[d], s2); }
    g_tvec[b*CC + c] = tv;
    g_scale[b*CC + c] = s1;
    g_shift[b*CC + c] = s2;
}

// ---------------- kA: forward DFT along w (m -> ky) ----------------
__global__ void __launch_bounds__(256) kA_fwd_ky(const float* __restrict__ x) {
    __shared__ float xs[32][WW + 1];
    int t = threadIdx.x;
    int R0 = blockIdx.x * 32;
    for (int q = 0; q < 16; q++) {
        int idx = t + 256*q;
        xs[idx >> 7][idx & 127] = x[(size_t)R0*WW + idx];
    }
    __syncthreads();
    int ky2 = t & 15, rp = t >> 4;
    int r0 = rp * 2;
    float ar[2][2] = {{0.f,0.f},{0.f,0.f}}, ai[2][2] = {{0.f,0.f},{0.f,0.f}};
    for (int m = 0; m < WW; m++) {
        float x0 = xs[r0][m], x1 = xs[r0 + 1][m];
        #pragma unroll
        for (int ks = 0; ks < 2; ks++) {
            float2 cs = g_tabJK[m*MM + ky2 + 16*ks];
            ar[0][ks] = fmaf(x0, cs.x, ar[0][ks]);
            ai[0][ks] = fmaf(-x0, cs.y, ai[0][ks]);
            ar[1][ks] = fmaf(x1, cs.x, ar[1][ks]);
            ai[1][ks] = fmaf(-x1, cs.y, ai[1][ks]);
        }
    }
    #pragma unroll
    for (int rr = 0; rr < 2; rr++)
        #pragma unroll
        for (int ks = 0; ks < 2; ks++)
            g_A[(size_t)(R0 + r0 + rr)*MM + ky2 + 16*ks] = make_float2(ar[rr][ks], ai[rr][ks]);
}

// ---------------- kB: forward DFT along h (n -> kx) ----------------
__global__ void __launch_bounds__(256) kB_fwd_kx() {
    __shared__ float2 sA[HH][MM];
    int t = threadIdx.x;
    int bc = blockIdx.x;
    const float2* Ap = g_A + (size_t)bc*HH*MM;
    for (int q = 0; q < 16; q++) ((float2*)sA)[t + 256*q] = Ap[t + 256*q];
    __syncthreads();
    int ky = t & 31, kxb = t >> 5;
    float sr[4] = {0,0,0,0}, si[4] = {0,0,0,0};
    for (int n = 0; n < HH; n++) {
        float2 a = sA[n][ky];
        #pragma unroll
        for (int j = 0; j < 4; j++) {
            float2 cs = g_tabJK[n*MM + kxb + 8*j];
            sr[j] = fmaf(a.x, cs.x, sr[j]); sr[j] = fmaf(a.y, cs.y, sr[j]);
            si[j] = fmaf(a.y, cs.x, si[j]); si[j] = fmaf(-a.x, cs.y, si[j]);
        }
    }
    const float scl = 1.f/128.f;
    #pragma unroll
    for (int j = 0; j < 4; j++) {
        int kx = kxb + 8*j;
        g_Smode[(size_t)bc*NMODE + kx*MM + ky] = make_float2(sr[j]*scl, si[j]*scl);
    }
}

// ---------------- kC: per-mode complex channel mix (4-stage cp.async pipeline) ----------------
__global__ void __launch_bounds__(256) kC_mix(const float* __restrict__ w_real,
                                              const float* __restrict__ w_imag) {
    __shared__ float2 sS[4][16][32];     // 16KB
    __shared__ float  sW[4][2][16][32];  // 16KB
    int t = threadIdx.x;
    int kx = blockIdx.x >> 4;
    int o0 = (blockIdx.x & 15) << 4;

    int sb = t >> 4, sf = t & 15;
    const float* wsrc = (t < 128) ? w_real : w_imag;
    int whalf = t >> 7, wo = (t >> 3) & 15, wf = t & 7;

    int ky = t & 31, bq = t >> 5;
    float ar0[16], ai0[16], ar1[16], ai1[16];
    #pragma unroll
    for (int o = 0; o < 16; o++) { ar0[o]=0.f; ai0[o]=0.f; ar1[o]=0.f; ai1[o]=0.f; }

    #pragma unroll
    for (int i = 0; i < 3; i++) {
        const float4* ssrc = (const float4*)g_Smode + (size_t)(sb*CC + i)*512 + kx*16 + sf;
        cpasync16(smem_u32(&sS[i][sb][sf*2]), ssrc);
        const float4* wsp = (const float4*)(wsrc + ((size_t)(i*CC + o0 + wo) << 10) + (kx << 5)) + wf;
        cpasync16(smem_u32(&sW[i][whalf][wo][wf*4]), wsp);
        cpcommit();
    }

    for (int i = 0; i < CC; i++) {
        if (i + 3 < CC) {
            int ip = i + 3, st2 = ip & 3;
            const float4* ssrc = (const float4*)g_Smode + (size_t)(sb*CC + ip)*512 + kx*16 + sf;
            cpasync16(smem_u32(&sS[st2][sb][sf*2]), ssrc);
            const float4* wsp = (const float4*)(wsrc + ((size_t)(ip*CC + o0 + wo) << 10) + (kx << 5)) + wf;
            cpasync16(smem_u32(&sW[st2][whalf][wo][wf*4]), wsp);
        }
        cpcommit();
        cpwait<3>();
        __syncthreads();
        int st = i & 3;
        float2 s0 = sS[st][bq][ky];
        float2 s1 = sS[st][bq + 8][ky];
        #pragma unroll
        for (int o = 0; o < 16; o++) {
            float wr = sW[st][0][o][ky], wi = sW[st][1][o][ky];
            ar0[o] = fmaf(s0.x, wr, ar0[o]); ar0[o] = fmaf(-s0.y, wi, ar0[o]);
            ai0[o] = fmaf(s0.x, wi, ai0[o]); ai0[o] = fmaf( s0.y, wr, ai0[o]);
            ar1[o] = fmaf(s1.x, wr, ar1[o]); ar1[o] = fmaf(-s1.y, wi, ar1[o]);
            ai1[o] = fmaf(s1.x, wi, ai1[o]); ai1[o] = fmaf( s1.y, wr, ai1[o]);
        }
        __syncthreads();
    }
    #pragma unroll
    for (int o = 0; o < 16; o++) {
        g_Omode[(((size_t)(bq*CC + o0 + o)) << 10) + (kx << 5) + ky]       = make_float2(ar0[o], ai0[o]);
        g_Omode[(((size_t)((bq+8)*CC + o0 + o)) << 10) + (kx << 5) + ky]   = make_float2(ar1[o], ai1[o]);
    }
}

// ---------------- kD: inverse DFT along kx ----------------
__global__ void __launch_bounds__(256) kD_inv_kx() {
    __shared__ float2 sO[MM][MM];
    int t = threadIdx.x;
    int bo = blockIdx.x;
    const float2* Op = g_Omode + (size_t)bo*NMODE;
    for (int q = 0; q < 4; q++) ((float2*)sO)[t + 256*q] = Op[t + 256*q];
    __syncthreads();
    int ky = t & 31, nq = t >> 5;
    float gr[16], gi[16];
    #pragma unroll
    for (int q = 0; q < 16; q++) { gr[q] = 0.f; gi[q] = 0.f; }
    for (int kx = 0; kx < MM; kx++) {
        float2 o = sO[kx][ky];
        #pragma unroll
        for (int q = 0; q < 16; q++) {
            int n = nq*16 + q;
            float2 cs = g_tabJK[n*MM + kx];
            gr[q] = fmaf(o.x, cs.x, gr[q]); gr[q] = fmaf(-o.y, cs.y, gr[q]);
            gi[q] = fmaf(o.x, cs.y, gi[q]); gi[q] = fmaf(o.y, cs.x, gi[q]);
        }
    }
    float fac = (ky == 0 ? 1.f : 2.f) * (1.f/128.f);
    #pragma unroll
    for (int q = 0; q < 16; q++) {
        int n = nq*16 + q;
        g_A[(size_t)bo*HH*MM + n*MM + ky] = make_float2(gr[q]*fac, gi[q]*fac);
    }
}

// ---------------- kE: inverse C2R along ky ----------------
__global__ void __launch_bounds__(256) kE_inv_m() {
    __shared__ float2 sG[64][MM];
    int t = threadIdx.x;
    int bo = blockIdx.x >> 1, nh = blockIdx.x & 1;
    const float2* Gp = g_A + (size_t)bo*HH*MM + (size_t)nh*64*MM;
    for (int q = 0; q < 8; q++) ((float2*)sG)[t + 256*q] = Gp[t + 256*q];
    __syncthreads();
    int m = t & 127, nq2 = t >> 7;
    float acc[32];
    #pragma unroll
    for (int i = 0; i < 32; i++) acc[i] = 0.f;
    for (int kc = 0; kc < 4; kc++) {
        float tc[8], ts[8];
        #pragma unroll
        for (int j = 0; j < 8; j++) {
            float2 cs = g_tabKJ[(kc*8 + j)*HH + m];
            tc[j] = cs.x; ts[j] = cs.y;
        }
        #pragma unroll
        for (int i = 0; i < 32; i++) {
            int nl = nq2*32 + i;
            #pragma unroll
            for (int j = 0; j < 8; j++) {
                float2 g = sG[nl][kc*8 + j];
                acc[i] = fmaf(g.x, tc[j], acc[i]);
                acc[i] = fmaf(-g.y, ts[j], acc[i]);
            }
        }
    }
    float* outp = g_h + (size_t)bo*HW + (size_t)(nh*64)*WW;
    #pragma unroll
    for (int i = 0; i < 32; i++)
        outp[(nq2*32 + i)*WW + m] = acc[i];
}

// ---------------- kF: pointwise GEMM via tf32 mma + fused epilogue + GN stats ----------------
#define ASM_(st,r,c) sdyn[(st)*4608 + (r)*36 + (c)]
#define BSM_(st,k,n) sdyn[9216 + (st)*4352 + (k)*136 + (n)]

__global__ void __launch_bounds__(256, 2) kF_mma(const float* __restrict__ x,
                                                 const float* __restrict__ pw_w,
                                                 const float* __restrict__ pw_b) {
    extern __shared__ float sdyn[];
    int t = threadIdx.x;
    int lane = t & 31, warp = t >> 5;
    int wm = warp >> 1, wn = warp & 1;
    int bi = blockIdx.x;
    int bb = bi >> 8;
    int ot = (bi >> 7) & 1, hwt = bi & 127;
    int o0 = ot * 128, hw0 = hwt * 128;

    float acc[2][8][4];
    #pragma unroll
    for (int mf = 0; mf < 2; mf++)
        #pragma unroll
        for (int nf = 0; nf < 8; nf++)
            #pragma unroll
            for (int e = 0; e < 4; e++) acc[mf][nf][e] = 0.f;

    {
        int i0 = 0;
        #pragma unroll
        for (int q = 0; q < 4; q++) {
            int idx = t + 256*q;
            int row = idx >> 3, c4 = idx & 7;
            cpasync16(smem_u32(&ASM_(0, row, c4*4)), pw_w + (size_t)(o0 + row)*CC + i0 + c4*4);
        }
        #pragma unroll
        for (int q = 0; q < 4; q++) {
            int idx = t + 256*q;
            int row = idx >> 5, c4 = idx & 31;
            cpasync16(smem_u32(&BSM_(0, row, c4*4)),
                      x + (((size_t)(bb*CC + i0 + row)) << 14) + hw0 + c4*4);
        }
        cpcommit();
    }

    for (int kc = 0; kc < 8; kc++) {
        if (kc + 1 < 8) {
            int i0 = (kc + 1) * 32, st2 = (kc + 1) & 1;
            #pragma unroll
            for (int q = 0; q < 4; q++) {
                int idx = t + 256*q;
                int row = idx >> 3, c4 = idx & 7;
                cpasync16(smem_u32(&ASM_(st2, row, c4*4)), pw_w + (size_t)(o0 + row)*CC + i0 + c4*4);
            }
            #pragma unroll
            for (int q = 0; q < 4; q++) {
                int idx = t + 256*q;
                int row = idx >> 5, c4 = idx & 31;
                cpasync16(smem_u32(&BSM_(st2, row, c4*4)),
                          x + (((size_t)(bb*CC + i0 + row)) << 14) + hw0 + c4*4);
            }
            cpcommit();
            cpwait<1>();
        } else {
            cpwait<0>();
        }
        __syncthreads();
        int st = kc & 1;
        #pragma unroll
        for (int k8 = 0; k8 < 4; k8++) {
            uint32_t a[2][4], b[8][2];
            int arow = wm*32 + (lane >> 2);
            int acol = (lane & 3) + k8*8;
            #pragma unroll
            for (int mf = 0; mf < 2; mf++) {
                int r = arow + mf*16;
                a[mf][0] = f2tf(ASM_(st, r,     acol));
                a[mf][1] = f2tf(ASM_(st, r + 8, acol));
                a[mf][2] = f2tf(ASM_(st, r,     acol + 4));
                a[mf][3] = f2tf(ASM_(st, r + 8, acol + 4));
            }
            int bk = (lane & 3) + k8*8;
            int bn0 = wn*64 + (lane >> 2);
            #pragma unroll
            for (int nf = 0; nf < 8; nf++) {
                b[nf][0] = f2tf(BSM_(st, bk,     bn0 + nf*8));
                b[nf][1] = f2tf(BSM_(st, bk + 4, bn0 + nf*8));
            }
            #pragma unroll
            for (int mf = 0; mf < 2; mf++)
                #pragma unroll
                for (int nf = 0; nf < 8; nf++)
                    mma_tf32(acc[mf][nf], a[mf], b[nf]);
        }
        __syncthreads();
    }

    float lsum = 0.f, lsum2 = 0.f;
    #pragma unroll
    for (int mf = 0; mf < 2; mf++) {
        int rbase = o0 + wm*32 + mf*16 + (lane >> 2);
        float addb[2], scl[2], shf[2];
        #pragma unroll
        for (int h = 0; h < 2; h++) {
            int o = rbase + 8*h;
            addb[h] = pw_b[o] + g_tvec[bb*CC + o];
            scl[h]  = 1.f + g_scale[bb*CC + o];
            shf[h]  = g_shift[bb*CC + o];
        }
        #pragma unroll
        for (int nf = 0; nf < 8; nf++) {
            int col = hw0 + wn*64 + nf*8 + 2*(lane & 3);
            #pragma unroll
            for (int h = 0; h < 2; h++) {
                size_t idx = (((size_t)(bb*CC + rbase + 8*h)) << 14) + col;
                float2 hv = *(float2*)&g_h[idx];
                float v0 = (acc[mf][nf][2*h]     + hv.x + addb[h]) * scl[h] + shf[h];
                float v1 = (acc[mf][nf][2*h + 1] + hv.y + addb[h]) * scl[h] + shf[h];
                *(float2*)&g_h[idx] = make_float2(v0, v1);
                lsum  += v0 + v1;
                lsum2 += v0*v0 + v1*v1;
            }
        }
    }
    #pragma unroll
    for (int off = 16; off; off >>= 1) {
        lsum  += __shfl_xor_sync(0xffffffffu, lsum, off);
        lsum2 += __shfl_xor_sync(0xffffffffu, lsum2, off);
    }
    if (lane == 0) {
        int g = (o0 + wm*32) >> 5;
        atomicAdd(&g_stats[(bb*NG + g)*2],     lsum);
        atomicAdd(&g_stats[(bb*NG + g)*2 + 1], lsum2);
    }
}

// ---------------- kG: finalize GroupNorm stats ----------------
__global__ void kG_stats() {
    int t = threadIdx.x;
    if (t < BB*NG) {
        float s = g_stats[t*2], s2 = g_stats[t*2 + 1];
        const float inv = 1.f / 524288.f;
        float mu = s * inv;
        float var = s2 * inv - mu*mu;
        g_stats[t*2]     = mu;
        g_stats[t*2 + 1] = rsqrtf(var + EPSV);
    }
}

// ---------------- kH: normalize + affine + GELU + residual ----------------
__device__ __forceinline__ float gelu_res(float h, float xr, float ga, float be) {
    float hn = fmaf(h, ga, be);
    return xr + 0.5f*hn*(1.f + erff(hn*0.70710678118654752f));
}

__global__ void __launch_bounds__(256) kH_final(const float* __restrict__ x,
                                                const float* __restrict__ gn_g,
                                                const float* __restrict__ gn_b,
                                                float* __restrict__ out) {
    int idx4 = blockIdx.x*256 + threadIdx.x;
    int base = idx4 << 2;
    int c = (base >> 14) & 255;
    int b = base >> 22;
    int g = c >> 5;
    float mu = g_stats[(b*NG + g)*2];
    float rs = g_stats[(b*NG + g)*2 + 1];
    float ga = gn_g[c] * rs;
    float be = gn_b[c] - mu * ga;
    float4 hv = ((const float4*)g_h)[idx4];
    float4 xv = ((const float4*)x)[idx4];
    float4 r;
    r.x = gelu_res(hv.x, xv.x, ga, be);
    r.y = gelu_res(hv.y, xv.y, ga, be);
    r.z = gelu_res(hv.z, xv.z, ga, be);
    r.w = gelu_res(hv.w, xv.w, ga, be);
    ((float4*)out)[idx4] = r;
}

extern "C" void kernel_launch(void* const* d_in, const int* in_sizes, int n_in,
                              void* d_out, int out_size) {
    const float* x        = (const float*)d_in[0];
    const float* t_emb    = (const float*)d_in[1];
    const float* cond_emb = (const float*)d_in[2];
    const float* w_real   = (const float*)d_in[3];
    const float* w_imag   = (const float*)d_in[4];
    const float* pw_w     = (const float*)d_in[5];
    const float* pw_b     = (const float*)d_in[6];
    const float* tp_w     = (const float*)d_in[7];
    const float* tp_b     = (const float*)d_in[8];
    const float* cp_w     = (const float*)d_in[9];
    const float* cp_b     = (const float*)d_in[10];
    const float* gn_g     = (const float*)d_in[11];
    const float* gn_b     = (const float*)d_in[12];
    float* out = (float*)d_out;

    static int smem_set = 0;
    if (!smem_set) {
        cudaFuncSetAttribute(kF_mma, cudaFuncAttributeMaxDynamicSharedMemorySize, 73728);
        smem_set = 1;
    }

    k0_prep<<<BB + 1, 256>>>(t_emb, cond_emb, tp_w, tp_b, cp_w, cp_b);
    kA_fwd_ky<<<16384, 256>>>(x);
    kB_fwd_kx<<<4096, 256>>>();
    kC_mix<<<512, 256>>>(w_real, w_imag);
    kD_inv_kx<<<4096, 256>>>();
    kE_inv_m<<<8192, 256>>>();
    kF_mma<<<4096, 256, 73728>>>(x, pw_w, pw_b);
    kG_stats<<<1, 256>>>();
    kH_final<<<65536, 256>>>(x, gn_g, gn_b, out);
}

// round 5
// speedup vs baseline: 1.7639x; 1.2665x over previous
#include <cuda_runtime.h>
#include <cstdint>
#include <math.h>

#define BB 16
#define CC 256
#define HH 128
#define WW 128
#define HW 16384
#define MM 32
#define NMODE 1024
#define TD 512
#define CD 512
#define NG 8
#define EPSV 1e-5f

// ---------------- persistent scratch ----------------
__device__ float2 g_A[(size_t)BB*CC*HH*MM];
__device__ float2 g_Smode[(size_t)BB*CC*NMODE];
__device__ float2 g_Omode[(size_t)BB*CC*NMODE];
__device__ float  g_h[(size_t)BB*CC*HW];
__device__ float  g_tvec[BB*CC];
__device__ float  g_scale[BB*CC];
__device__ float  g_shift[BB*CC];
__device__ float  g_stats[BB*NG*2];
__device__ float2 g_tabJK[HH*MM];
__device__ float2 g_tabKJ[MM*HH];

// ---------------- helpers ----------------
__device__ __forceinline__ uint32_t smem_u32(const void* p) {
    return (uint32_t)__cvta_generic_to_shared(p);
}
__device__ __forceinline__ void cpasync16(uint32_t dst, const void* src) {
    asm volatile("cp.async.ca.shared.global [%0], [%1], 16;" :: "r"(dst), "l"(src));
}
__device__ __forceinline__ void cpcommit() { asm volatile("cp.async.commit_group;"); }
template<int N>
__device__ __forceinline__ void cpwait() { asm volatile("cp.async.wait_group %0;" :: "n"(N)); }
__device__ __forceinline__ uint32_t f2tf(float v) {
    uint32_t r;
    asm("cvt.rna.tf32.f32 %0, %1;" : "=r"(r) : "f"(v));
    return r;
}
__device__ __forceinline__ void mma_tf32(float* d, const uint32_t* a, const uint32_t* b) {
    asm volatile("mma.sync.aligned.m16n8k8.row.col.f32.tf32.tf32.f32 "
                 "{%0,%1,%2,%3}, {%4,%5,%6,%7}, {%8,%9}, {%0,%1,%2,%3};"
                 : "+f"(d[0]), "+f"(d[1]), "+f"(d[2]), "+f"(d[3])
                 : "r"(a[0]), "r"(a[1]), "r"(a[2]), "r"(a[3]), "r"(b[0]), "r"(b[1]));
}

// ---------------- K0: tables + embedding projections + zero stats ----------------
__global__ void k0_prep(const float* __restrict__ t_emb, const float* __restrict__ cond_emb,
                        const float* __restrict__ tp_w, const float* __restrict__ tp_b,
                        const float* __restrict__ cp_w, const float* __restrict__ cp_b) {
    int t = threadIdx.x;
    if (blockIdx.x == BB) {
        for (int e = t; e < HH*MM; e += 256) {
            int j = e >> 5, k = e & 31;
            float ang = (float)((j * k) & 127) * 0.049087385212340517f;
            float s, c; sincosf(ang, &s, &c);
            g_tabJK[j*MM + k] = make_float2(c, s);
            g_tabKJ[k*HH + j] = make_float2(c, s);
        }
        if (t < BB*NG*2) g_stats[t] = 0.f;
        return;
    }
    int b = blockIdx.x;
    __shared__ float st[TD];
    __shared__ float sc[CD];
    for (int e = t; e < TD; e += 256) { float v = t_emb[b*TD + e];   st[e] = v / (1.f + expf(-v)); }
    for (int e = t; e < CD; e += 256) { float v = cond_emb[b*CD + e]; sc[e] = v / (1.f + expf(-v)); }
    __syncthreads();
    int c = t;
    float tv = tp_b[c], s1 = cp_b[c], s2 = cp_b[c + CC];
    const float* tw = tp_w + (size_t)c*TD;
    const float* c1 = cp_w + (size_t)c*CD;
    const float* c2 = cp_w + (size_t)(c + CC)*CD;
    for (int d = 0; d < TD; d++) tv = fmaf(st[d], tw[d], tv);
    for (int d = 0; d < CD; d++) { s1 = fmaf(sc[d], c1[d], s1); s2 = fmaf(sc[d], c2[d], s2); }
    g_tvec[b*CC + c] = tv;
    g_scale[b*CC + c] = s1;
    g_shift[b*CC + c] = s2;
}

// ---------------- kA: forward ky-DFT as tf32 GEMM ----------------
// C[R=524288 x 64] = X[R x 128] @ T[128 x 64]; T[m][2ky]=cos, T[m][2ky+1]=-sin.
// Block: 128 rows. smem: TS[128][68] @0 (8704 f), XS[2][128][36] @8704.
#define TSA_(k,n)      sdyn[(k)*68 + (n)]
#define XSA_(st,r,k)   sdyn[8704 + (st)*4608 + (r)*36 + (k)]

__global__ void __launch_bounds__(256, 2) kA_mma(const float* __restrict__ x) {
    extern __shared__ float sdyn[];
    int t = threadIdx.x, lane = t & 31, warp = t >> 5;
    int wm = warp >> 1, wn = warp & 1;
    int R0 = blockIdx.x * 128;

    for (int e = t; e < HH*MM; e += 256) {
        int m = e >> 5, ky = e & 31;
        float2 cs = g_tabJK[e];           // e = m*32 + ky
        TSA_(m, 2*ky)     = cs.x;
        TSA_(m, 2*ky + 1) = -cs.y;
    }
    // prologue: X chunk 0
    #pragma unroll
    for (int q = 0; q < 4; q++) {
        int idx = t + 256*q;
        int row = idx >> 3, c4 = idx & 7;
        cpasync16(smem_u32(&XSA_(0, row, c4*4)), x + (size_t)(R0 + row)*128 + c4*4);
    }
    cpcommit();

    float acc[2][4][4];
    #pragma unroll
    for (int mf = 0; mf < 2; mf++)
        #pragma unroll
        for (int nf = 0; nf < 4; nf++)
            #pragma unroll
            for (int e = 0; e < 4; e++) acc[mf][nf][e] = 0.f;

    for (int kc = 0; kc < 4; kc++) {
        if (kc + 1 < 4) {
            int k0 = (kc + 1) * 32, st2 = (kc + 1) & 1;
            #pragma unroll
            for (int q = 0; q < 4; q++) {
                int idx = t + 256*q;
                int row = idx >> 3, c4 = idx & 7;
                cpasync16(smem_u32(&XSA_(st2, row, c4*4)), x + (size_t)(R0 + row)*128 + k0 + c4*4);
            }
            cpcommit();
            cpwait<1>();
        } else {
            cpwait<0>();
        }
        __syncthreads();
        int st = kc & 1;
        #pragma unroll
        for (int k8 = 0; k8 < 4; k8++) {
            uint32_t a[2][4], b[4][2];
            int arow = wm*32 + (lane >> 2);
            int acol = (lane & 3) + k8*8;
            #pragma unroll
            for (int mf = 0; mf < 2; mf++) {
                int r = arow + mf*16;
                a[mf][0] = f2tf(XSA_(st, r,     acol));
                a[mf][1] = f2tf(XSA_(st, r + 8, acol));
                a[mf][2] = f2tf(XSA_(st, r,     acol + 4));
                a[mf][3] = f2tf(XSA_(st, r + 8, acol + 4));
            }
            int kg = kc*32 + k8*8 + (lane & 3);
            int bn0 = wn*32 + (lane >> 2);
            #pragma unroll
            for (int nf = 0; nf < 4; nf++) {
                b[nf][0] = f2tf(TSA_(kg,     bn0 + nf*8));
                b[nf][1] = f2tf(TSA_(kg + 4, bn0 + nf*8));
            }
            #pragma unroll
            for (int mf = 0; mf < 2; mf++)
                #pragma unroll
                for (int nf = 0; nf < 4; nf++)
                    mma_tf32(acc[mf][nf], a[mf], b[nf]);
        }
        __syncthreads();
    }
    float* Ao = (float*)g_A;
    #pragma unroll
    for (int mf = 0; mf < 2; mf++) {
        int r = R0 + wm*32 + mf*16 + (lane >> 2);
        #pragma unroll
        for (int nf = 0; nf < 4; nf++) {
            int col = wn*32 + nf*8 + 2*(lane & 3);
            *(float2*)&Ao[(size_t)r*64 + col]       = make_float2(acc[mf][nf][0], acc[mf][nf][1]);
            *(float2*)&Ao[(size_t)(r + 8)*64 + col] = make_float2(acc[mf][nf][2], acc[mf][nf][3]);
        }
    }
}

// ---------------- kB: forward DFT along h (n -> kx) ----------------
__global__ void __launch_bounds__(256) kB_fwd_kx() {
    __shared__ float2 sA[HH][MM];
    int t = threadIdx.x;
    int bc = blockIdx.x;
    const float2* Ap = g_A + (size_t)bc*HH*MM;
    for (int q = 0; q < 16; q++) ((float2*)sA)[t + 256*q] = Ap[t + 256*q];
    __syncthreads();
    int ky = t & 31, kxb = t >> 5;
    float sr[4] = {0,0,0,0}, si[4] = {0,0,0,0};
    for (int n = 0; n < HH; n++) {
        float2 a = sA[n][ky];
        #pragma unroll
        for (int j = 0; j < 4; j++) {
            float2 cs = g_tabJK[n*MM + kxb + 8*j];
            sr[j] = fmaf(a.x, cs.x, sr[j]); sr[j] = fmaf(a.y, cs.y, sr[j]);
            si[j] = fmaf(a.y, cs.x, si[j]); si[j] = fmaf(-a.x, cs.y, si[j]);
        }
    }
    const float scl = 1.f/128.f;
    #pragma unroll
    for (int j = 0; j < 4; j++) {
        int kx = kxb + 8*j;
        g_Smode[(size_t)bc*NMODE + kx*MM + ky] = make_float2(sr[j]*scl, si[j]*scl);
    }
}

// ---------------- kC: per-mode complex channel mix (4-stage cp.async pipeline) ----------------
__global__ void __launch_bounds__(256) kC_mix(const float* __restrict__ w_real,
                                              const float* __restrict__ w_imag) {
    __shared__ float2 sS[4][16][32];
    __shared__ float  sW[4][2][16][32];
    int t = threadIdx.x;
    int kx = blockIdx.x >> 4;
    int o0 = (blockIdx.x & 15) << 4;

    int sb = t >> 4, sf = t & 15;
    const float* wsrc = (t < 128) ? w_real : w_imag;
    int whalf = t >> 7, wo = (t >> 3) & 15, wf = t & 7;

    int ky = t & 31, bq = t >> 5;
    float ar0[16], ai0[16], ar1[16], ai1[16];
    #pragma unroll
    for (int o = 0; o < 16; o++) { ar0[o]=0.f; ai0[o]=0.f; ar1[o]=0.f; ai1[o]=0.f; }

    #pragma unroll
    for (int i = 0; i < 3; i++) {
        const float4* ssrc = (const float4*)g_Smode + (size_t)(sb*CC + i)*512 + kx*16 + sf;
        cpasync16(smem_u32(&sS[i][sb][sf*2]), ssrc);
        const float4* wsp = (const float4*)(wsrc + ((size_t)(i*CC + o0 + wo) << 10) + (kx << 5)) + wf;
        cpasync16(smem_u32(&sW[i][whalf][wo][wf*4]), wsp);
        cpcommit();
    }

    for (int i = 0; i < CC; i++) {
        if (i + 3 < CC) {
            int ip = i + 3, st2 = ip & 3;
            const float4* ssrc = (const float4*)g_Smode + (size_t)(sb*CC + ip)*512 + kx*16 + sf;
            cpasync16(smem_u32(&sS[st2][sb][sf*2]), ssrc);
            const float4* wsp = (const float4*)(wsrc + ((size_t)(ip*CC + o0 + wo) << 10) + (kx << 5)) + wf;
            cpasync16(smem_u32(&sW[st2][whalf][wo][wf*4]), wsp);
        }
        cpcommit();
        cpwait<3>();
        __syncthreads();
        int st = i & 3;
        float2 s0 = sS[st][bq][ky];
        float2 s1 = sS[st][bq + 8][ky];
        #pragma unroll
        for (int o = 0; o < 16; o++) {
            float wr = sW[st][0][o][ky], wi = sW[st][1][o][ky];
            ar0[o] = fmaf(s0.x, wr, ar0[o]); ar0[o] = fmaf(-s0.y, wi, ar0[o]);
            ai0[o] = fmaf(s0.x, wi, ai0[o]); ai0[o] = fmaf( s0.y, wr, ai0[o]);
            ar1[o] = fmaf(s1.x, wr, ar1[o]); ar1[o] = fmaf(-s1.y, wi, ar1[o]);
            ai1[o] = fmaf(s1.x, wi, ai1[o]); ai1[o] = fmaf( s1.y, wr, ai1[o]);
        }
        __syncthreads();
    }
    #pragma unroll
    for (int o = 0; o < 16; o++) {
        g_Omode[(((size_t)(bq*CC + o0 + o)) << 10) + (kx << 5) + ky]       = make_float2(ar0[o], ai0[o]);
        g_Omode[(((size_t)((bq+8)*CC + o0 + o)) << 10) + (kx << 5) + ky]   = make_float2(ar1[o], ai1[o]);
    }
}

// ---------------- kD: inverse DFT along kx ----------------
__global__ void __launch_bounds__(256) kD_inv_kx() {
    __shared__ float2 sO[MM][MM];
    int t = threadIdx.x;
    int bo = blockIdx.x;
    const float2* Op = g_Omode + (size_t)bo*NMODE;
    for (int q = 0; q < 4; q++) ((float2*)sO)[t + 256*q] = Op[t + 256*q];
    __syncthreads();
    int ky = t & 31, nq = t >> 5;
    float gr[16], gi[16];
    #pragma unroll
    for (int q = 0; q < 16; q++) { gr[q] = 0.f; gi[q] = 0.f; }
    for (int kx = 0; kx < MM; kx++) {
        float2 o = sO[kx][ky];
        #pragma unroll
        for (int q = 0; q < 16; q++) {
            int n = nq*16 + q;
            float2 cs = g_tabJK[n*MM + kx];
            gr[q] = fmaf(o.x, cs.x, gr[q]); gr[q] = fmaf(-o.y, cs.y, gr[q]);
            gi[q] = fmaf(o.x, cs.y, gi[q]); gi[q] = fmaf(o.y, cs.x, gi[q]);
        }
    }
    float fac = (ky == 0 ? 1.f : 2.f) * (1.f/128.f);
    #pragma unroll
    for (int q = 0; q < 16; q++) {
        int n = nq*16 + q;
        g_A[(size_t)bo*HH*MM + n*MM + ky] = make_float2(gr[q]*fac, gi[q]*fac);
    }
}

// ---------------- kE: inverse C2R along ky as tf32 GEMM ----------------
// out[R x 128] = G[R x 64] @ U[64 x 128]; U[2ky][m]=cos, U[2ky+1][m]=-sin.
// smem: GS[128][68] @0 (8704 f), US[64][132] @8704 (8448 f)
#define GSE_(r,k)   sdyn[(r)*68 + (k)]
#define USE_(k,n)   sdyn[8704 + (k)*132 + (n)]

__global__ void __launch_bounds__(256, 2) kE_mma() {
    extern __shared__ float sdyn[];
    int t = threadIdx.x, lane = t & 31, warp = t >> 5;
    int wm = warp >> 1, wn = warp & 1;
    int R0 = blockIdx.x * 128;

    for (int e = t; e < MM*HH; e += 256) {
        int ky = e >> 7, m = e & 127;
        float2 cs = g_tabKJ[e];           // e = ky*128 + m
        USE_(2*ky,     m) = cs.x;
        USE_(2*ky + 1, m) = -cs.y;
    }
    const float* Gp = (const float*)g_A;
    #pragma unroll
    for (int q = 0; q < 8; q++) {
        int idx = t + 256*q;
        int row = idx >> 4, c4 = idx & 15;
        cpasync16(smem_u32(&GSE_(row, c4*4)), Gp + (size_t)(R0 + row)*64 + c4*4);
    }
    cpcommit();
    cpwait<0>();
    __syncthreads();

    float acc[2][8][4];
    #pragma unroll
    for (int mf = 0; mf < 2; mf++)
        #pragma unroll
        for (int nf = 0; nf < 8; nf++)
            #pragma unroll
            for (int e = 0; e < 4; e++) acc[mf][nf][e] = 0.f;

    #pragma unroll
    for (int k8 = 0; k8 < 8; k8++) {
        uint32_t a[2][4], b[8][2];
        int arow = wm*32 + (lane >> 2);
        int acol = (lane & 3) + k8*8;
        #pragma unroll
        for (int mf = 0; mf < 2; mf++) {
            int r = arow + mf*16;
            a[mf][0] = f2tf(GSE_(r,     acol));
            a[mf][1] = f2tf(GSE_(r + 8, acol));
            a[mf][2] = f2tf(GSE_(r,     acol + 4));
            a[mf][3] = f2tf(GSE_(r + 8, acol + 4));
        }
        int kg = k8*8 + (lane & 3);
        int bn0 = wn*64 + (lane >> 2);
        #pragma unroll
        for (int nf = 0; nf < 8; nf++) {
            b[nf][0] = f2tf(USE_(kg,     bn0 + nf*8));
            b[nf][1] = f2tf(USE_(kg + 4, bn0 + nf*8));
        }
        #pragma unroll
        for (int mf = 0; mf < 2; mf++)
            #pragma unroll
            for (int nf = 0; nf < 8; nf++)
                mma_tf32(acc[mf][nf], a[mf], b[nf]);
    }

    #pragma unroll
    for (int mf = 0; mf < 2; mf++) {
        int r = R0 + wm*32 + mf*16 + (lane >> 2);
        #pragma unroll
        for (int nf = 0; nf < 8; nf++) {
            int col = wn*64 + nf*8 + 2*(lane & 3);
            *(float2*)&g_h[(size_t)r*128 + col]       = make_float2(acc[mf][nf][0], acc[mf][nf][1]);
            *(float2*)&g_h[(size_t)(r + 8)*128 + col] = make_float2(acc[mf][nf][2], acc[mf][nf][3]);
        }
    }
}

// ---------------- kF: pointwise GEMM via tf32 mma + fused epilogue + GN stats ----------------
#define ASM_(st,r,c) sdyn[(st)*4608 + (r)*36 + (c)]
#define BSM_(st,k,n) sdyn[9216 + (st)*4352 + (k)*136 + (n)]

__global__ void __launch_bounds__(256, 2) kF_mma(const float* __restrict__ x,
                                                 const float* __restrict__ pw_w,
                                                 const float* __restrict__ pw_b) {
    extern __shared__ float sdyn[];
    int t = threadIdx.x;
    int lane = t & 31, warp = t >> 5;
    int wm = warp >> 1, wn = warp & 1;
    int bi = blockIdx.x;
    int bb = bi >> 8;
    int ot = (bi >> 7) & 1, hwt = bi & 127;
    int o0 = ot * 128, hw0 = hwt * 128;

    float acc[2][8][4];
    #pragma unroll
    for (int mf = 0; mf < 2; mf++)
        #pragma unroll
        for (int nf = 0; nf < 8; nf++)
            #pragma unroll
            for (int e = 0; e < 4; e++) acc[mf][nf][e] = 0.f;

    {
        int i0 = 0;
        #pragma unroll
        for (int q = 0; q < 4; q++) {
            int idx = t + 256*q;
            int row = idx >> 3, c4 = idx & 7;
            cpasync16(smem_u32(&ASM_(0, row, c4*4)), pw_w + (size_t)(o0 + row)*CC + i0 + c4*4);
        }
        #pragma unroll
        for (int q = 0; q < 4; q++) {
            int idx = t + 256*q;
            int row = idx >> 5, c4 = idx & 31;
            cpasync16(smem_u32(&BSM_(0, row, c4*4)),
                      x + (((size_t)(bb*CC + i0 + row)) << 14) + hw0 + c4*4);
        }
        cpcommit();
    }

    for (int kc = 0; kc < 8; kc++) {
        if (kc + 1 < 8) {
            int i0 = (kc + 1) * 32, st2 = (kc + 1) & 1;
            #pragma unroll
            for (int q = 0; q < 4; q++) {
                int idx = t + 256*q;
                int row = idx >> 3, c4 = idx & 7;
                cpasync16(smem_u32(&ASM_(st2, row, c4*4)), pw_w + (size_t)(o0 + row)*CC + i0 + c4*4);
            }
            #pragma unroll
            for (int q = 0; q < 4; q++) {
                int idx = t + 256*q;
                int row = idx >> 5, c4 = idx & 31;
                cpasync16(smem_u32(&BSM_(st2, row, c4*4)),
                          x + (((size_t)(bb*CC + i0 + row)) << 14) + hw0 + c4*4);
            }
            cpcommit();
            cpwait<1>();
        } else {
            cpwait<0>();
        }
        __syncthreads();
        int st = kc & 1;
        #pragma unroll
        for (int k8 = 0; k8 < 4; k8++) {
            uint32_t a[2][4], b[8][2];
            int arow = wm*32 + (lane >> 2);
            int acol = (lane & 3) + k8*8;
            #pragma unroll
            for (int mf = 0; mf < 2; mf++) {
                int r = arow + mf*16;
                a[mf][0] = f2tf(ASM_(st, r,     acol));
                a[mf][1] = f2tf(ASM_(st, r + 8, acol));
                a[mf][2] = f2tf(ASM_(st, r,     acol + 4));
                a[mf][3] = f2tf(ASM_(st, r + 8, acol + 4));
            }
            int bk = (lane & 3) + k8*8;
            int bn0 = wn*64 + (lane >> 2);
            #pragma unroll
            for (int nf = 0; nf < 8; nf++) {
                b[nf][0] = f2tf(BSM_(st, bk,     bn0 + nf*8));
                b[nf][1] = f2tf(BSM_(st, bk + 4, bn0 + nf*8));
            }
            #pragma unroll
            for (int mf = 0; mf < 2; mf++)
                #pragma unroll
                for (int nf = 0; nf < 8; nf++)
                    mma_tf32(acc[mf][nf], a[mf], b[nf]);
        }
        __syncthreads();
    }

    float lsum = 0.f, lsum2 = 0.f;
    #pragma unroll
    for (int mf = 0; mf < 2; mf++) {
        int rbase = o0 + wm*32 + mf*16 + (lane >> 2);
        float addb[2], scl[2], shf[2];
        #pragma unroll
        for (int h = 0; h < 2; h++) {
            int o = rbase + 8*h;
            addb[h] = pw_b[o] + g_tvec[bb*CC + o];
            scl[h]  = 1.f + g_scale[bb*CC + o];
            shf[h]  = g_shift[bb*CC + o];
        }
        #pragma unroll
        for (int nf = 0; nf < 8; nf++) {
            int col = hw0 + wn*64 + nf*8 + 2*(lane & 3);
            #pragma unroll
            for (int h = 0; h < 2; h++) {
                size_t idx = (((size_t)(bb*CC + rbase + 8*h)) << 14) + col;
                float2 hv = *(float2*)&g_h[idx];
                float v0 = (acc[mf][nf][2*h]     + hv.x + addb[h]) * scl[h] + shf[h];
                float v1 = (acc[mf][nf][2*h + 1] + hv.y + addb[h]) * scl[h] + shf[h];
                *(float2*)&g_h[idx] = make_float2(v0, v1);
                lsum  += v0 + v1;
                lsum2 += v0*v0 + v1*v1;
            }
        }
    }
    #pragma unroll
    for (int off = 16; off; off >>= 1) {
        lsum  += __shfl_xor_sync(0xffffffffu, lsum, off);
        lsum2 += __shfl_xor_sync(0xffffffffu, lsum2, off);
    }
    if (lane == 0) {
        int g = (o0 + wm*32) >> 5;
        atomicAdd(&g_stats[(bb*NG + g)*2],     lsum);
        atomicAdd(&g_stats[(bb*NG + g)*2 + 1], lsum2);
    }
}

// ---------------- kG: finalize GroupNorm stats ----------------
__global__ void kG_stats() {
    int t = threadIdx.x;
    if (t < BB*NG) {
        float s = g_stats[t*2], s2 = g_stats[t*2 + 1];
        const float inv = 1.f / 524288.f;
        float mu = s * inv;
        float var = s2 * inv - mu*mu;
        g_stats[t*2]     = mu;
        g_stats[t*2 + 1] = rsqrtf(var + EPSV);
    }
}

// ---------------- kH: normalize + affine + GELU + residual ----------------
__device__ __forceinline__ float gelu_res(float h, float xr, float ga, float be) {
    float hn = fmaf(h, ga, be);
    return xr + 0.5f*hn*(1.f + erff(hn*0.70710678118654752f));
}

__global__ void __launch_bounds__(256) kH_final(const float* __restrict__ x,
                                                const float* __restrict__ gn_g,
                                                const float* __restrict__ gn_b,
                                                float* __restrict__ out) {
    int idx4 = blockIdx.x*256 + threadIdx.x;
    int base = idx4 << 2;
    int c = (base >> 14) & 255;
    int b = base >> 22;
    int g = c >> 5;
    float mu = g_stats[(b*NG + g)*2];
    float rs = g_stats[(b*NG + g)*2 + 1];
    float ga = gn_g[c] * rs;
    float be = gn_b[c] - mu * ga;
    float4 hv = ((const float4*)g_h)[idx4];
    float4 xv = ((const float4*)x)[idx4];
    float4 r;
    r.x = gelu_res(hv.x, xv.x, ga, be);
    r.y = gelu_res(hv.y, xv.y, ga, be);
    r.z = gelu_res(hv.z, xv.z, ga, be);
    r.w = gelu_res(hv.w, xv.w, ga, be);
    ((float4*)out)[idx4] = r;
}

extern "C" void kernel_launch(void* const* d_in, const int* in_sizes, int n_in,
                              void* d_out, int out_size) {
    const float* x        = (const float*)d_in[0];
    const float* t_emb    = (const float*)d_in[1];
    const float* cond_emb = (const float*)d_in[2];
    const float* w_real   = (const float*)d_in[3];
    const float* w_imag   = (const float*)d_in[4];
    const float* pw_w     = (const float*)d_in[5];
    const float* pw_b     = (const float*)d_in[6];
    const float* tp_w     = (const float*)d_in[7];
    const float* tp_b     = (const float*)d_in[8];
    const float* cp_w     = (const float*)d_in[9];
    const float* cp_b     = (const float*)d_in[10];
    const float* gn_g     = (const float*)d_in[11];
    const float* gn_b     = (const float*)d_in[12];
    float* out = (float*)d_out;

    static int smem_set = 0;
    if (!smem_set) {
        cudaFuncSetAttribute(kF_mma, cudaFuncAttributeMaxDynamicSharedMemorySize, 73728);
        cudaFuncSetAttribute(kA_mma, cudaFuncAttributeMaxDynamicSharedMemorySize, 71680);
        cudaFuncSetAttribute(kE_mma, cudaFuncAttributeMaxDynamicSharedMemorySize, 68608);
        smem_set = 1;
    }

    k0_prep<<<BB + 1, 256>>>(t_emb, cond_emb, tp_w, tp_b, cp_w, cp_b);
    kA_mma<<<4096, 256, 71680>>>(x);
    kB_fwd_kx<<<4096, 256>>>();
    kC_mix<<<512, 256>>>(w_real, w_imag);
    kD_inv_kx<<<4096, 256>>>();
    kE_mma<<<4096, 256, 68608>>>();
    kF_mma<<<4096, 256, 73728>>>(x, pw_w, pw_b);
    kG_stats<<<1, 256>>>();
    kH_final<<<65536, 256>>>(x, gn_g, gn_b, out);
}

// round 6
// speedup vs baseline: 1.8354x; 1.0405x over previous
#include <cuda_runtime.h>
#include <cstdint>
#include <math.h>

#define BB 16
#define CC 256
#define HH 128
#define WW 128
#define HW 16384
#define MM 32
#define NMODE 1024
#define TD 512
#define CD 512
#define NG 8
#define EPSV 1e-5f

typedef unsigned long long u64;

// ---------------- persistent scratch ----------------
__device__ float2 g_A[(size_t)BB*CC*HH*MM];      // kA out (rows of 64 floats, (r,i) interleaved); reused by kD out
__device__ float2 g_Smode[(size_t)BB*CC*NMODE];  // reused as SoA: [bc][kx][32r+32i]
__device__ float2 g_Omode[(size_t)BB*CC*NMODE];  // reused as SoA
__device__ float  g_h[(size_t)BB*CC*HW];
__device__ float  g_tvec[BB*CC];
__device__ float  g_scale[BB*CC];
__device__ float  g_shift[BB*CC];
__device__ float  g_stats[BB*NG*2];
__device__ float2 g_tabJK[HH*MM];
__device__ float2 g_tabKJ[MM*HH];

// ---------------- helpers ----------------
__device__ __forceinline__ uint32_t smem_u32(const void* p) {
    return (uint32_t)__cvta_generic_to_shared(p);
}
__device__ __forceinline__ void cpasync16(uint32_t dst, const void* src) {
    asm volatile("cp.async.ca.shared.global [%0], [%1], 16;" :: "r"(dst), "l"(src));
}
__device__ __forceinline__ void cpcommit() { asm volatile("cp.async.commit_group;"); }
template<int N>
__device__ __forceinline__ void cpwait() { asm volatile("cp.async.wait_group %0;" :: "n"(N)); }
__device__ __forceinline__ uint32_t f2tf(float v) {
    uint32_t r;
    asm("cvt.rna.tf32.f32 %0, %1;" : "=r"(r) : "f"(v));
    return r;
}
__device__ __forceinline__ void mma_tf32(float* d, const uint32_t* a, const uint32_t* b) {
    asm volatile("mma.sync.aligned.m16n8k8.row.col.f32.tf32.tf32.f32 "
                 "{%0,%1,%2,%3}, {%4,%5,%6,%7}, {%8,%9}, {%0,%1,%2,%3};"
                 : "+f"(d[0]), "+f"(d[1]), "+f"(d[2]), "+f"(d[3])
                 : "r"(a[0]), "r"(a[1]), "r"(a[2]), "r"(a[3]), "r"(b[0]), "r"(b[1]));
}
// packed f32x2
__device__ __forceinline__ u64 pack2(float x, float y) {
    u64 r; asm("mov.b64 %0, {%1, %2};" : "=l"(r) : "f"(x), "f"(y)); return r;
}
__device__ __forceinline__ u64 fma2(u64 a, u64 b, u64 c) {
    u64 d; asm("fma.rn.f32x2 %0, %1, %2, %3;" : "=l"(d) : "l"(a), "l"(b), "l"(c)); return d;
}
__device__ __forceinline__ u64 neg2(u64 a) { return a ^ 0x8000000080000000ULL; }
__device__ __forceinline__ float2 unpack2(u64 a) {
    float2 v; asm("mov.b64 {%0, %1}, %2;" : "=f"(v.x), "=f"(v.y) : "l"(a)); return v;
}

// ---------------- K0: tables + embedding projections + zero stats ----------------
__global__ void k0_prep(const float* __restrict__ t_emb, const float* __restrict__ cond_emb,
                        const float* __restrict__ tp_w, const float* __restrict__ tp_b,
                        const float* __restrict__ cp_w, const float* __restrict__ cp_b) {
    int t = threadIdx.x;
    if (blockIdx.x == BB) {
        for (int e = t; e < HH*MM; e += 256) {
            int j = e >> 5, k = e & 31;
            float ang = (float)((j * k) & 127) * 0.049087385212340517f;
            float s, c; sincosf(ang, &s, &c);
            g_tabJK[j*MM + k] = make_float2(c, s);
            g_tabKJ[k*HH + j] = make_float2(c, s);
        }
        if (t < BB*NG*2) g_stats[t] = 0.f;
        return;
    }
    int b = blockIdx.x;
    __shared__ float st[TD];
    __shared__ float sc[CD];
    for (int e = t; e < TD; e += 256) { float v = t_emb[b*TD + e];   st[e] = v / (1.f + expf(-v)); }
    for (int e = t; e < CD; e += 256) { float v = cond_emb[b*CD + e]; sc[e] = v / (1.f + expf(-v)); }
    __syncthreads();
    int c = t;
    float tv = tp_b[c], s1 = cp_b[c], s2 = cp_b[c + CC];
    const float* tw = tp_w + (size_t)c*TD;
    const float* c1 = cp_w + (size_t)c*CD;
    const float* c2 = cp_w + (size_t)(c + CC)*CD;
    for (int d = 0; d < TD; d++) tv = fmaf(st[d], tw[d], tv);
    for (int d = 0; d < CD; d++) { s1 = fmaf(sc[d], c1[d], s1); s2 = fmaf(sc[d], c2[d], s2); }
    g_tvec[b*CC + c] = tv;
    g_scale[b*CC + c] = s1;
    g_shift[b*CC + c] = s2;
}

// ---------------- kA: forward ky-DFT as tf32 GEMM ----------------
#define TSA_(k,n)      sdyn[(k)*68 + (n)]
#define XSA_(st,r,k)   sdyn[8704 + (st)*4608 + (r)*36 + (k)]

__global__ void __launch_bounds__(256, 2) kA_mma(const float* __restrict__ x) {
    extern __shared__ float sdyn[];
    int t = threadIdx.x, lane = t & 31, warp = t >> 5;
    int wm = warp >> 1, wn = warp & 1;
    int R0 = blockIdx.x * 128;

    for (int e = t; e < HH*MM; e += 256) {
        int m = e >> 5, ky = e & 31;
        float2 cs = g_tabJK[e];
        TSA_(m, 2*ky)     = cs.x;
        TSA_(m, 2*ky + 1) = -cs.y;
    }
    #pragma unroll
    for (int q = 0; q < 4; q++) {
        int idx = t + 256*q;
        int row = idx >> 3, c4 = idx & 7;
        cpasync16(smem_u32(&XSA_(0, row, c4*4)), x + (size_t)(R0 + row)*128 + c4*4);
    }
    cpcommit();

    float acc[2][4][4];
    #pragma unroll
    for (int mf = 0; mf < 2; mf++)
        #pragma unroll
        for (int nf = 0; nf < 4; nf++)
            #pragma unroll
            for (int e = 0; e < 4; e++) acc[mf][nf][e] = 0.f;

    for (int kc = 0; kc < 4; kc++) {
        if (kc + 1 < 4) {
            int k0 = (kc + 1) * 32, st2 = (kc + 1) & 1;
            #pragma unroll
            for (int q = 0; q < 4; q++) {
                int idx = t + 256*q;
                int row = idx >> 3, c4 = idx & 7;
                cpasync16(smem_u32(&XSA_(st2, row, c4*4)), x + (size_t)(R0 + row)*128 + k0 + c4*4);
            }
            cpcommit();
            cpwait<1>();
        } else {
            cpwait<0>();
        }
        __syncthreads();
        int st = kc & 1;
        #pragma unroll
        for (int k8 = 0; k8 < 4; k8++) {
            uint32_t a[2][4], b[4][2];
            int arow = wm*32 + (lane >> 2);
            int acol = (lane & 3) + k8*8;
            #pragma unroll
            for (int mf = 0; mf < 2; mf++) {
                int r = arow + mf*16;
                a[mf][0] = f2tf(XSA_(st, r,     acol));
                a[mf][1] = f2tf(XSA_(st, r + 8, acol));
                a[mf][2] = f2tf(XSA_(st, r,     acol + 4));
                a[mf][3] = f2tf(XSA_(st, r + 8, acol + 4));
            }
            int kg = kc*32 + k8*8 + (lane & 3);
            int bn0 = wn*32 + (lane >> 2);
            #pragma unroll
            for (int nf = 0; nf < 4; nf++) {
                b[nf][0] = f2tf(TSA_(kg,     bn0 + nf*8));
                b[nf][1] = f2tf(TSA_(kg + 4, bn0 + nf*8));
            }
            #pragma unroll
            for (int mf = 0; mf < 2; mf++)
                #pragma unroll
                for (int nf = 0; nf < 4; nf++)
                    mma_tf32(acc[mf][nf], a[mf], b[nf]);
        }
        __syncthreads();
    }
    float* Ao = (float*)g_A;
    #pragma unroll
    for (int mf = 0; mf < 2; mf++) {
        int r = R0 + wm*32 + mf*16 + (lane >> 2);
        #pragma unroll
        for (int nf = 0; nf < 4; nf++) {
            int col = wn*32 + nf*8 + 2*(lane & 3);
            *(float2*)&Ao[(size_t)r*64 + col]       = make_float2(acc[mf][nf][0], acc[mf][nf][1]);
            *(float2*)&Ao[(size_t)(r + 8)*64 + col] = make_float2(acc[mf][nf][2], acc[mf][nf][3]);
        }
    }
}

// ---------------- kB: forward DFT along h, packed f32x2; 2 channels per CTA ----------------
// out S[kx][ky]: Sr = sum_n Ar*c + Ai*s ; Si = sum_n Ai*c - Ar*s   (c,s at [n][kx])
// output layout SoA: g_SmF[bc*2048 + kx*64 + ky] = real, +32 = imag
#define TCB_(n,kx)    dynB[(n)*32 + (kx)]
#define TSB_(n,kx)    dynB[4096 + (n)*32 + (kx)]
#define SAB_(sl,n,c)  dynB[8192 + (sl)*8192 + (n)*64 + (c)]

__global__ void __launch_bounds__(256, 2) kB_pack() {
    extern __shared__ float dynB[];
    int t = threadIdx.x;
    int bc0 = blockIdx.x * 2;
    for (int e = t; e < 4096; e += 256) {
        float2 cs = g_tabJK[e];       // e = n*32 + kx
        TCB_(e >> 5, e & 31) = cs.x;
        TSB_(e >> 5, e & 31) = cs.y;
    }
    {
        const float4* src = (const float4*)((const float*)g_A + (size_t)bc0*8192);
        float4* dst = (float4*)&dynB[8192];
        #pragma unroll
        for (int q = 0; q < 16; q++) dst[t + 256*q] = src[t + 256*q];
    }
    __syncthreads();

    int sl = t >> 7, u = t & 127;
    int ky = u & 31, grp = u >> 5;      // grp 0..3 -> 4 kx-pairs each
    u64 Srp[4], Sip[4];
    #pragma unroll
    for (int j = 0; j < 4; j++) { Srp[j] = 0ULL; Sip[j] = 0ULL; }

    for (int n = 0; n < HH; n++) {
        float2 a = *(float2*)&SAB_(sl, n, 2*ky);       // (Ar, Ai)
        u64 arr = pack2(a.x, a.x);
        u64 aii = pack2(a.y, a.y);
        u64 nar = pack2(-a.x, -a.x);
        #pragma unroll
        for (int j = 0; j < 4; j++) {
            int kxp = grp*4 + j;
            u64 cp = *(u64*)&TCB_(n, 2*kxp);
            u64 sp = *(u64*)&TSB_(n, 2*kxp);
            Srp[j] = fma2(arr, cp, fma2(aii, sp, Srp[j]));
            Sip[j] = fma2(aii, cp, fma2(nar, sp, Sip[j]));
        }
    }
    const float scl = 1.f/128.f;
    float* So = (float*)g_Smode + (size_t)(bc0 + sl)*2048;
    #pragma unroll
    for (int j = 0; j < 4; j++) {
        int kxp = grp*4 + j;
        float2 r = unpack2(Srp[j]);
        float2 im = unpack2(Sip[j]);
        So[(2*kxp)*64 + ky]          = r.x*scl;
        So[(2*kxp + 1)*64 + ky]      = r.y*scl;
        So[(2*kxp)*64 + 32 + ky]     = im.x*scl;
        So[(2*kxp + 1)*64 + 32 + ky] = im.y*scl;
    }
}

// ---------------- kC: per-mode complex channel mix, packed f32x2, 4-stage cp.async ----------------
__global__ void __launch_bounds__(256) kC_pack(const float* __restrict__ w_real,
                                               const float* __restrict__ w_imag) {
    __shared__ float sS[4][16][64];      // 16KB  [stage][b][32 real + 32 imag]
    __shared__ float sW[4][2][16][32];   // 16KB
    int t = threadIdx.x;
    int kx = blockIdx.x >> 4;
    int o0 = (blockIdx.x & 15) << 4;

    int sb = t >> 4, sf = t & 15;
    const float* wsrc = (t < 128) ? w_real : w_imag;
    int whalf = t >> 7, wo = (t >> 3) & 15, wf = t & 7;

    int kyp = t & 15, bp = (t >> 4) & 7, oh = t >> 7;
    u64 arp[2][8], aip[2][8];
    #pragma unroll
    for (int bh = 0; bh < 2; bh++)
        #pragma unroll
        for (int o = 0; o < 8; o++) { arp[bh][o] = 0ULL; aip[bh][o] = 0ULL; }

    const float* SmF = (const float*)g_Smode;
    #pragma unroll
    for (int i = 0; i < 3; i++) {
        cpasync16(smem_u32(&sS[i][sb][sf*4]), SmF + (size_t)(sb*CC + i)*2048 + kx*64 + sf*4);
        const float4* wsp = (const float4*)(wsrc + ((size_t)(i*CC + o0 + wo) << 10) + (kx << 5)) + wf;
        cpasync16(smem_u32(&sW[i][whalf][wo][wf*4]), wsp);
        cpcommit();
    }

    for (int i = 0; i < CC; i++) {
        if (i + 3 < CC) {
            int ip = i + 3, st2 = ip & 3;
            cpasync16(smem_u32(&sS[st2][sb][sf*4]), SmF + (size_t)(sb*CC + ip)*2048 + kx*64 + sf*4);
            const float4* wsp = (const float4*)(wsrc + ((size_t)(ip*CC + o0 + wo) << 10) + (kx << 5)) + wf;
            cpasync16(smem_u32(&sW[st2][whalf][wo][wf*4]), wsp);
        }
        cpcommit();
        cpwait<3>();
        __syncthreads();
        int st = i & 3;
        u64 sx0 = *(u64*)&sS[st][bp][2*kyp];
        u64 sy0 = *(u64*)&sS[st][bp][32 + 2*kyp];
        u64 sx1 = *(u64*)&sS[st][bp + 8][2*kyp];
        u64 sy1 = *(u64*)&sS[st][bp + 8][32 + 2*kyp];
        u64 nsy0 = neg2(sy0), nsy1 = neg2(sy1);
        #pragma unroll
        for (int o = 0; o < 8; o++) {
            u64 wrp = *(u64*)&sW[st][0][oh*8 + o][2*kyp];
            u64 wip = *(u64*)&sW[st][1][oh*8 + o][2*kyp];
            arp[0][o] = fma2(sx0, wrp, fma2(nsy0, wip, arp[0][o]));
            aip[0][o] = fma2(sx0, wip, fma2(sy0,  wrp, aip[0][o]));
            arp[1][o] = fma2(sx1, wrp, fma2(nsy1, wip, arp[1][o]));
            aip[1][o] = fma2(sx1, wip, fma2(sy1,  wrp, aip[1][o]));
        }
        __syncthreads();
    }
    float* OmF = (float*)g_Omode;
    #pragma unroll
    for (int bh = 0; bh < 2; bh++) {
        int b = bp + 8*bh;
        #pragma unroll
        for (int o = 0; o < 8; o++) {
            float* dst = OmF + (size_t)(b*CC + o0 + oh*8 + o)*2048 + kx*64;
            *(float2*)&dst[2*kyp]      = unpack2(arp[bh][o]);
            *(float2*)&dst[32 + 2*kyp] = unpack2(aip[bh][o]);
        }
    }
}

// ---------------- kD: inverse kx-DFT, packed f32x2 ----------------
// G[n][ky]: Gr = sum_kx Or*c - Oi*s ; Gi = sum_kx Or*s + Oi*c  (c,s at [n][kx], e^{+i})
// writes interleaved rows for kE: g_A[(bo*128+n)*64 + 2ky] = Gr*fac, +1 = Gi*fac
__global__ void __launch_bounds__(256) kD_pack() {
    __shared__ float tabCT[32][128];   // [kx][n]
    __shared__ float tabST[32][128];
    __shared__ float sO[32][64];       // [kx][32r+32i]
    int t = threadIdx.x;
    int bo = blockIdx.x;
    for (int e = t; e < 4096; e += 256) {
        int kx = e >> 7, n = e & 127;
        float2 cs = g_tabJK[n*32 + kx];
        tabCT[kx][n] = cs.x;
        tabST[kx][n] = cs.y;
    }
    {
        const float4* src = (const float4*)((const float*)g_Omode + (size_t)bo*2048);
        #pragma unroll
        for (int q = 0; q < 2; q++) ((float4*)sO)[t + 256*q] = src[t + 256*q];
    }
    __syncthreads();

    int ky = t & 31, npg = t >> 5;   // npg 0..7, each 8 n-pairs (16 n)
    u64 Grp[8], Gip[8];
    #pragma unroll
    for (int j = 0; j < 8; j++) { Grp[j] = 0ULL; Gip[j] = 0ULL; }

    for (int kx = 0; kx < MM; kx++) {
        float Or = sO[kx][ky], Oi = sO[kx][32 + ky];
        u64 Orr = pack2(Or, Or);
        u64 Oii = pack2(Oi, Oi);
        u64 nOii = pack2(-Oi, -Oi);
        #pragma unroll
        for (int j = 0; j < 8; j++) {
            int n0 = npg*16 + 2*j;
            u64 cp = *(u64*)&tabCT[kx][n0];
            u64 sp = *(u64*)&tabST[kx][n0];
            Grp[j] = fma2(Orr, cp, fma2(nOii, sp, Grp[j]));
            Gip[j] = fma2(Orr, sp, fma2(Oii,  cp, Gip[j]));
        }
    }
    float fac = (ky == 0 ? 1.f : 2.f) * (1.f/128.f);
    float* Ao = (float*)g_A + (size_t)bo*8192;
    #pragma unroll
    for (int j = 0; j < 8; j++) {
        int n0 = npg*16 + 2*j;
        float2 gr = unpack2(Grp[j]);
        float2 gi = unpack2(Gip[j]);
        *(float2*)&Ao[(size_t)n0*64 + 2*ky]       = make_float2(gr.x*fac, gi.x*fac);
        *(float2*)&Ao[(size_t)(n0 + 1)*64 + 2*ky] = make_float2(gr.y*fac, gi.y*fac);
    }
}

// ---------------- kE: inverse C2R along ky as tf32 GEMM ----------------
#define GSE_(r,k)   sdyn[(r)*68 + (k)]
#define USE_(k,n)   sdyn[8704 + (k)*132 + (n)]

__global__ void __launch_bounds__(256, 2) kE_mma() {
    extern __shared__ float sdyn[];
    int t = threadIdx.x, lane = t & 31, warp = t >> 5;
    int wm = warp >> 1, wn = warp & 1;
    int R0 = blockIdx.x * 128;

    for (int e = t; e < MM*HH; e += 256) {
        int ky = e >> 7, m = e & 127;
        float2 cs = g_tabKJ[e];
        USE_(2*ky,     m) = cs.x;
        USE_(2*ky + 1, m) = -cs.y;
    }
    const float* Gp = (const float*)g_A;
    #pragma unroll
    for (int q = 0; q < 8; q++) {
        int idx = t + 256*q;
        int row = idx >> 4, c4 = idx & 15;
        cpasync16(smem_u32(&GSE_(row, c4*4)), Gp + (size_t)(R0 + row)*64 + c4*4);
    }
    cpcommit();
    cpwait<0>();
    __syncthreads();

    float acc[2][8][4];
    #pragma unroll
    for (int mf = 0; mf < 2; mf++)
        #pragma unroll
        for (int nf = 0; nf < 8; nf++)
            #pragma unroll
            for (int e = 0; e < 4; e++) acc[mf][nf][e] = 0.f;

    #pragma unroll
    for (int k8 = 0; k8 < 8; k8++) {
        uint32_t a[2][4], b[8][2];
        int arow = wm*32 + (lane >> 2);
        int acol = (lane & 3) + k8*8;
        #pragma unroll
        for (int mf = 0; mf < 2; mf++) {
            int r = arow + mf*16;
            a[mf][0] = f2tf(GSE_(r,     acol));
            a[mf][1] = f2tf(GSE_(r + 8, acol));
            a[mf][2] = f2tf(GSE_(r,     acol + 4));
            a[mf][3] = f2tf(GSE_(r + 8, acol + 4));
        }
        int kg = k8*8 + (lane & 3);
        int bn0 = wn*64 + (lane >> 2);
        #pragma unroll
        for (int nf = 0; nf < 8; nf++) {
            b[nf][0] = f2tf(USE_(kg,     bn0 + nf*8));
            b[nf][1] = f2tf(USE_(kg + 4, bn0 + nf*8));
        }
        #pragma unroll
        for (int mf = 0; mf < 2; mf++)
            #pragma unroll
            for (int nf = 0; nf < 8; nf++)
                mma_tf32(acc[mf][nf], a[mf], b[nf]);
    }

    #pragma unroll
    for (int mf = 0; mf < 2; mf++) {
        int r = R0 + wm*32 + mf*16 + (lane >> 2);
        #pragma unroll
        for (int nf = 0; nf < 8; nf++) {
            int col = wn*64 + nf*8 + 2*(lane & 3);
            *(float2*)&g_h[(size_t)r*128 + col]       = make_float2(acc[mf][nf][0], acc[mf][nf][1]);
            *(float2*)&g_h[(size_t)(r + 8)*128 + col] = make_float2(acc[mf][nf][2], acc[mf][nf][3]);
        }
    }
}

// ---------------- kF: pointwise GEMM via tf32 mma + fused epilogue + GN stats ----------------
#define ASM_(st,r,c) sdyn[(st)*4608 + (r)*36 + (c)]
#define BSM_(st,k,n) sdyn[9216 + (st)*4352 + (k)*136 + (n)]

__global__ void __launch_bounds__(256, 2) kF_mma(const float* __restrict__ x,
                                                 const float* __restrict__ pw_w,
                                                 const float* __restrict__ pw_b) {
    extern __shared__ float sdyn[];
    int t = threadIdx.x;
    int lane = t & 31, warp = t >> 5;
    int wm = warp >> 1, wn = warp & 1;
    int bi = blockIdx.x;
    int bb = bi >> 8;
    int ot = (bi >> 7) & 1, hwt = bi & 127;
    int o0 = ot * 128, hw0 = hwt * 128;

    float acc[2][8][4];
    #pragma unroll
    for (int mf = 0; mf < 2; mf++)
        #pragma unroll
        for (int nf = 0; nf < 8; nf++)
            #pragma unroll
            for (int e = 0; e < 4; e++) acc[mf][nf][e] = 0.f;

    {
        int i0 = 0;
        #pragma unroll
        for (int q = 0; q < 4; q++) {
            int idx = t + 256*q;
            int row = idx >> 3, c4 = idx & 7;
            cpasync16(smem_u32(&ASM_(0, row, c4*4)), pw_w + (size_t)(o0 + row)*CC + i0 + c4*4);
        }
        #pragma unroll
        for (int q = 0; q < 4; q++) {
            int idx = t + 256*q;
            int row = idx >> 5, c4 = idx & 31;
            cpasync16(smem_u32(&BSM_(0, row, c4*4)),
                      x + (((size_t)(bb*CC + i0 + row)) << 14) + hw0 + c4*4);
        }
        cpcommit();
    }

    for (int kc = 0; kc < 8; kc++) {
        if (kc + 1 < 8) {
            int i0 = (kc + 1) * 32, st2 = (kc + 1) & 1;
            #pragma unroll
            for (int q = 0; q < 4; q++) {
                int idx = t + 256*q;
                int row = idx >> 3, c4 = idx & 7;
                cpasync16(smem_u32(&ASM_(st2, row, c4*4)), pw_w + (size_t)(o0 + row)*CC + i0 + c4*4);
            }
            #pragma unroll
            for (int q = 0; q < 4; q++) {
                int idx = t + 256*q;
                int row = idx >> 5, c4 = idx & 31;
                cpasync16(smem_u32(&BSM_(st2, row, c4*4)),
                          x + (((size_t)(bb*CC + i0 + row)) << 14) + hw0 + c4*4);
            }
            cpcommit();
            cpwait<1>();
        } else {
            cpwait<0>();
        }
        __syncthreads();
        int st = kc & 1;
        #pragma unroll
        for (int k8 = 0; k8 < 4; k8++) {
            uint32_t a[2][4], b[8][2];
            int arow = wm*32 + (lane >> 2);
            int acol = (lane & 3) + k8*8;
            #pragma unroll
            for (int mf = 0; mf < 2; mf++) {
                int r = arow + mf*16;
                a[mf][0] = f2tf(ASM_(st, r,     acol));
                a[mf][1] = f2tf(ASM_(st, r + 8, acol));
                a[mf][2] = f2tf(ASM_(st, r,     acol + 4));
                a[mf][3] = f2tf(ASM_(st, r + 8, acol + 4));
            }
            int bk = (lane & 3) + k8*8;
            int bn0 = wn*64 + (lane >> 2);
            #pragma unroll
            for (int nf = 0; nf < 8; nf++) {
                b[nf][0] = f2tf(BSM_(st, bk,     bn0 + nf*8));
                b[nf][1] = f2tf(BSM_(st, bk + 4, bn0 + nf*8));
            }
            #pragma unroll
            for (int mf = 0; mf < 2; mf++)
                #pragma unroll
                for (int nf = 0; nf < 8; nf++)
                    mma_tf32(acc[mf][nf], a[mf], b[nf]);
        }
        __syncthreads();
    }

    float lsum = 0.f, lsum2 = 0.f;
    #pragma unroll
    for (int mf = 0; mf < 2; mf++) {
        int rbase = o0 + wm*32 + mf*16 + (lane >> 2);
        float addb[2], scl[2], shf[2];
        #pragma unroll
        for (int h = 0; h < 2; h++) {
            int o = rbase + 8*h;
            addb[h] = pw_b[o] + g_tvec[bb*CC + o];
            scl[h]  = 1.f + g_scale[bb*CC + o];
            shf[h]  = g_shift[bb*CC + o];
        }
        #pragma unroll
        for (int nf = 0; nf < 8; nf++) {
            int col = hw0 + wn*64 + nf*8 + 2*(lane & 3);
            #pragma unroll
            for (int h = 0; h < 2; h++) {
                size_t idx = (((size_t)(bb*CC + rbase + 8*h)) << 14) + col;
                float2 hv = *(float2*)&g_h[idx];
                float v0 = (acc[mf][nf][2*h]     + hv.x + addb[h]) * scl[h] + shf[h];
                float v1 = (acc[mf][nf][2*h + 1] + hv.y + addb[h]) * scl[h] + shf[h];
                *(float2*)&g_h[idx] = make_float2(v0, v1);
                lsum  += v0 + v1;
                lsum2 += v0*v0 + v1*v1;
            }
        }
    }
    #pragma unroll
    for (int off = 16; off; off >>= 1) {
        lsum  += __shfl_xor_sync(0xffffffffu, lsum, off);
        lsum2 += __shfl_xor_sync(0xffffffffu, lsum2, off);
    }
    if (lane == 0) {
        int g = (o0 + wm*32) >> 5;
        atomicAdd(&g_stats[(bb*NG + g)*2],     lsum);
        atomicAdd(&g_stats[(bb*NG + g)*2 + 1], lsum2);
    }
}

// ---------------- kG: finalize GroupNorm stats ----------------
__global__ void kG_stats() {
    int t = threadIdx.x;
    if (t < BB*NG) {
        float s = g_stats[t*2], s2 = g_stats[t*2 + 1];
        const float inv = 1.f / 524288.f;
        float mu = s * inv;
        float var = s2 * inv - mu*mu;
        g_stats[t*2]     = mu;
        g_stats[t*2 + 1] = rsqrtf(var + EPSV);
    }
}

// ---------------- kH: normalize + affine + GELU + residual ----------------
__device__ __forceinline__ float gelu_res(float h, float xr, float ga, float be) {
    float hn = fmaf(h, ga, be);
    return xr + 0.5f*hn*(1.f + erff(hn*0.70710678118654752f));
}

__global__ void __launch_bounds__(256) kH_final(const float* __restrict__ x,
                                                const float* __restrict__ gn_g,
                                                const float* __restrict__ gn_b,
                                                float* __restrict__ out) {
    int idx4 = blockIdx.x*256 + threadIdx.x;
    int base = idx4 << 2;
    int c = (base >> 14) & 255;
    int b = base >> 22;
    int g = c >> 5;
    float mu = g_stats[(b*NG + g)*2];
    float rs = g_stats[(b*NG + g)*2 + 1];
    float ga = gn_g[c] * rs;
    float be = gn_b[c] - mu * ga;
    float4 hv = ((const float4*)g_h)[idx4];
    float4 xv = ((const float4*)x)[idx4];
    float4 r;
    r.x = gelu_res(hv.x, xv.x, ga, be);
    r.y = gelu_res(hv.y, xv.y, ga, be);
    r.z = gelu_res(hv.z, xv.z, ga, be);
    r.w = gelu_res(hv.w, xv.w, ga, be);
    ((float4*)out)[idx4] = r;
}

extern "C" void kernel_launch(void* const* d_in, const int* in_sizes, int n_in,
                              void* d_out, int out_size) {
    const float* x        = (const float*)d_in[0];
    const float* t_emb    = (const float*)d_in[1];
    const float* cond_emb = (const float*)d_in[2];
    const float* w_real   = (const float*)d_in[3];
    const float* w_imag   = (const float*)d_in[4];
    const float* pw_w     = (const float*)d_in[5];
    const float* pw_b     = (const float*)d_in[6];
    const float* tp_w     = (const float*)d_in[7];
    const float* tp_b     = (const float*)d_in[8];
    const float* cp_w     = (const float*)d_in[9];
    const float* cp_b     = (const float*)d_in[10];
    const float* gn_g     = (const float*)d_in[11];
    const float* gn_b     = (const float*)d_in[12];
    float* out = (float*)d_out;

    static int smem_set = 0;
    if (!smem_set) {
        cudaFuncSetAttribute(kF_mma, cudaFuncAttributeMaxDynamicSharedMemorySize, 73728);
        cudaFuncSetAttribute(kA_mma, cudaFuncAttributeMaxDynamicSharedMemorySize, 71680);
        cudaFuncSetAttribute(kE_mma, cudaFuncAttributeMaxDynamicSharedMemorySize, 68608);
        cudaFuncSetAttribute(kB_pack, cudaFuncAttributeMaxDynamicSharedMemorySize, 98304);
        smem_set = 1;
    }

    k0_prep<<<BB + 1, 256>>>(t_emb, cond_emb, tp_w, tp_b, cp_w, cp_b);
    kA_mma<<<4096, 256, 71680>>>(x);
    kB_pack<<<2048, 256, 98304>>>();
    kC_pack<<<512, 256>>>(w_real, w_imag);
    kD_pack<<<4096, 256>>>();
    kE_mma<<<4096, 256, 68608>>>();
    kF_mma<<<4096, 256, 73728>>>(x, pw_w, pw_b);
    kG_stats<<<1, 256>>>();
    kH_final<<<65536, 256>>>(x, gn_g, gn_b, out);
}

// round 7
// speedup vs baseline: 1.8558x; 1.0111x over previous
#include <cuda_runtime.h>
#include <cstdint>
#include <math.h>

#define BB 16
#define CC 256
#define HH 128
#define WW 128
#define HW 16384
#define MM 32
#define NMODE 1024
#define TD 512
#define CD 512
#define NG 8
#define EPSV 1e-5f

typedef unsigned long long u64;

// ---------------- persistent scratch ----------------
__device__ float2 g_A[(size_t)BB*CC*HH*MM];
__device__ float2 g_Smode[(size_t)BB*CC*NMODE];  // SoA per kx: 64 floats = 16 groups (r,r,i,i)
__device__ float2 g_Omode[(size_t)BB*CC*NMODE];  // SoA per kx: 32 real + 32 imag
__device__ float  g_h[(size_t)BB*CC*HW];
__device__ float  g_tvec[BB*CC];
__device__ float  g_scale[BB*CC];
__device__ float  g_shift[BB*CC];
__device__ float  g_stats[BB*NG*2];
__device__ float2 g_tabJK[HH*MM];
__device__ float2 g_tabKJ[MM*HH];

// ---------------- helpers ----------------
__device__ __forceinline__ uint32_t smem_u32(const void* p) {
    return (uint32_t)__cvta_generic_to_shared(p);
}
__device__ __forceinline__ void cpasync16(uint32_t dst, const void* src) {
    asm volatile("cp.async.ca.shared.global [%0], [%1], 16;" :: "r"(dst), "l"(src));
}
__device__ __forceinline__ void cpcommit() { asm volatile("cp.async.commit_group;"); }
template<int N>
__device__ __forceinline__ void cpwait() { asm volatile("cp.async.wait_group %0;" :: "n"(N)); }
__device__ __forceinline__ uint32_t f2tf(float v) {
    uint32_t r;
    asm("cvt.rna.tf32.f32 %0, %1;" : "=r"(r) : "f"(v));
    return r;
}
__device__ __forceinline__ void mma_tf32(float* d, const uint32_t* a, const uint32_t* b) {
    asm volatile("mma.sync.aligned.m16n8k8.row.col.f32.tf32.tf32.f32 "
                 "{%0,%1,%2,%3}, {%4,%5,%6,%7}, {%8,%9}, {%0,%1,%2,%3};"
                 : "+f"(d[0]), "+f"(d[1]), "+f"(d[2]), "+f"(d[3])
                 : "r"(a[0]), "r"(a[1]), "r"(a[2]), "r"(a[3]), "r"(b[0]), "r"(b[1]));
}
__device__ __forceinline__ u64 pack2(float x, float y) {
    u64 r; asm("mov.b64 %0, {%1, %2};" : "=l"(r) : "f"(x), "f"(y)); return r;
}
__device__ __forceinline__ u64 fma2(u64 a, u64 b, u64 c) {
    u64 d; asm("fma.rn.f32x2 %0, %1, %2, %3;" : "=l"(d) : "l"(a), "l"(b), "l"(c)); return d;
}
__device__ __forceinline__ u64 neg2(u64 a) { return a ^ 0x8000000080000000ULL; }
__device__ __forceinline__ float2 unpack2(u64 a) {
    float2 v; asm("mov.b64 {%0, %1}, %2;" : "=f"(v.x), "=f"(v.y) : "l"(a)); return v;
}

// ---------------- K0 ----------------
__global__ void k0_prep(const float* __restrict__ t_emb, const float* __restrict__ cond_emb,
                        const float* __restrict__ tp_w, const float* __restrict__ tp_b,
                        const float* __restrict__ cp_w, const float* __restrict__ cp_b) {
    int t = threadIdx.x;
    if (blockIdx.x == BB) {
        for (int e = t; e < HH*MM; e += 256) {
            int j = e >> 5, k = e & 31;
            float ang = (float)((j * k) & 127) * 0.049087385212340517f;
            float s, c; sincosf(ang, &s, &c);
            g_tabJK[j*MM + k] = make_float2(c, s);
            g_tabKJ[k*HH + j] = make_float2(c, s);
        }
        if (t < BB*NG*2) g_stats[t] = 0.f;
        return;
    }
    int b = blockIdx.x;
    __shared__ float st[TD];
    __shared__ float sc[CD];
    for (int e = t; e < TD; e += 256) { float v = t_emb[b*TD + e];   st[e] = v / (1.f + expf(-v)); }
    for (int e = t; e < CD; e += 256) { float v = cond_emb[b*CD + e]; sc[e] = v / (1.f + expf(-v)); }
    __syncthreads();
    int c = t;
    float tv = tp_b[c], s1 = cp_b[c], s2 = cp_b[c + CC];
    const float* tw = tp_w + (size_t)c*TD;
    const float* c1 = cp_w + (size_t)c*CD;
    const float* c2 = cp_w + (size_t)(c + CC)*CD;
    for (int d = 0; d < TD; d++) tv = fmaf(st[d], tw[d], tv);
    for (int d = 0; d < CD; d++) { s1 = fmaf(sc[d], c1[d], s1); s2 = fmaf(sc[d], c2[d], s2); }
    g_tvec[b*CC + c] = tv;
    g_scale[b*CC + c] = s1;
    g_shift[b*CC + c] = s2;
}

// ---------------- kA: forward ky-DFT as tf32 GEMM ----------------
#define TSA_(k,n)      sdyn[(k)*68 + (n)]
#define XSA_(st,r,k)   sdyn[8704 + (st)*4608 + (r)*36 + (k)]

__global__ void __launch_bounds__(256, 2) kA_mma(const float* __restrict__ x) {
    extern __shared__ float sdyn[];
    int t = threadIdx.x, lane = t & 31, warp = t >> 5;
    int wm = warp >> 1, wn = warp & 1;
    int R0 = blockIdx.x * 128;

    for (int e = t; e < HH*MM; e += 256) {
        int m = e >> 5, ky = e & 31;
        float2 cs = g_tabJK[e];
        TSA_(m, 2*ky)     = cs.x;
        TSA_(m, 2*ky + 1) = -cs.y;
    }
    #pragma unroll
    for (int q = 0; q < 4; q++) {
        int idx = t + 256*q;
        int row = idx >> 3, c4 = idx & 7;
        cpasync16(smem_u32(&XSA_(0, row, c4*4)), x + (size_t)(R0 + row)*128 + c4*4);
    }
    cpcommit();

    float acc[2][4][4];
    #pragma unroll
    for (int mf = 0; mf < 2; mf++)
        #pragma unroll
        for (int nf = 0; nf < 4; nf++)
            #pragma unroll
            for (int e = 0; e < 4; e++) acc[mf][nf][e] = 0.f;

    for (int kc = 0; kc < 4; kc++) {
        if (kc + 1 < 4) {
            int k0 = (kc + 1) * 32, st2 = (kc + 1) & 1;
            #pragma unroll
            for (int q = 0; q < 4; q++) {
                int idx = t + 256*q;
                int row = idx >> 3, c4 = idx & 7;
                cpasync16(smem_u32(&XSA_(st2, row, c4*4)), x + (size_t)(R0 + row)*128 + k0 + c4*4);
            }
            cpcommit();
            cpwait<1>();
        } else {
            cpwait<0>();
        }
        __syncthreads();
        int st = kc & 1;
        #pragma unroll
        for (int k8 = 0; k8 < 4; k8++) {
            uint32_t a[2][4], b[4][2];
            int arow = wm*32 + (lane >> 2);
            int acol = (lane & 3) + k8*8;
            #pragma unroll
            for (int mf = 0; mf < 2; mf++) {
                int r = arow + mf*16;
                a[mf][0] = f2tf(XSA_(st, r,     acol));
                a[mf][1] = f2tf(XSA_(st, r + 8, acol));
                a[mf][2] = f2tf(XSA_(st, r,     acol + 4));
                a[mf][3] = f2tf(XSA_(st, r + 8, acol + 4));
            }
            int kg = kc*32 + k8*8 + (lane & 3);
            int bn0 = wn*32 + (lane >> 2);
            #pragma unroll
            for (int nf = 0; nf < 4; nf++) {
                b[nf][0] = f2tf(TSA_(kg,     bn0 + nf*8));
                b[nf][1] = f2tf(TSA_(kg + 4, bn0 + nf*8));
            }
            #pragma unroll
            for (int mf = 0; mf < 2; mf++)
                #pragma unroll
                for (int nf = 0; nf < 4; nf++)
                    mma_tf32(acc[mf][nf], a[mf], b[nf]);
        }
        __syncthreads();
    }
    float* Ao = (float*)g_A;
    #pragma unroll
    for (int mf = 0; mf < 2; mf++) {
        int r = R0 + wm*32 + mf*16 + (lane >> 2);
        #pragma unroll
        for (int nf = 0; nf < 4; nf++) {
            int col = wn*32 + nf*8 + 2*(lane & 3);
            *(float2*)&Ao[(size_t)r*64 + col]       = make_float2(acc[mf][nf][0], acc[mf][nf][1]);
            *(float2*)&Ao[(size_t)(r + 8)*64 + col] = make_float2(acc[mf][nf][2], acc[mf][nf][3]);
        }
    }
}

// ---------------- kB: forward DFT along h, packed f32x2; rrii-group output ----------------
#define TCB_(n,kx)    dynB[(n)*32 + (kx)]
#define TSB_(n,kx)    dynB[4096 + (n)*32 + (kx)]
#define SAB_(sl,n,c)  dynB[8192 + (sl)*8192 + (n)*64 + (c)]

__global__ void __launch_bounds__(256, 2) kB_pack() {
    extern __shared__ float dynB[];
    int t = threadIdx.x;
    int bc0 = blockIdx.x * 2;
    for (int e = t; e < 4096; e += 256) {
        float2 cs = g_tabJK[e];       // e = n*32 + kx
        TCB_(e >> 5, e & 31) = cs.x;
        TSB_(e >> 5, e & 31) = cs.y;
    }
    {
        const float4* src = (const float4*)((const float*)g_A + (size_t)bc0*8192);
        float4* dst = (float4*)&dynB[8192];
        #pragma unroll
        for (int q = 0; q < 16; q++) dst[t + 256*q] = src[t + 256*q];
    }
    __syncthreads();

    int sl = t >> 7, u = t & 127;
    int ky = u & 31, grp = u >> 5;
    u64 Srp[4], Sip[4];
    #pragma unroll
    for (int j = 0; j < 4; j++) { Srp[j] = 0ULL; Sip[j] = 0ULL; }

    for (int n = 0; n < HH; n++) {
        float2 a = *(float2*)&SAB_(sl, n, 2*ky);
        u64 arr = pack2(a.x, a.x);
        u64 aii = pack2(a.y, a.y);
        u64 nar = pack2(-a.x, -a.x);
        #pragma unroll
        for (int j = 0; j < 4; j++) {
            int kxp = grp*4 + j;
            u64 cp = *(u64*)&TCB_(n, 2*kxp);
            u64 sp = *(u64*)&TSB_(n, 2*kxp);
            Srp[j] = fma2(arr, cp, fma2(aii, sp, Srp[j]));
            Sip[j] = fma2(aii, cp, fma2(nar, sp, Sip[j]));
        }
    }
    const float scl = 1.f/128.f;
    float* So = (float*)g_Smode + (size_t)(bc0 + sl)*2048;
    int off = (ky >> 1)*4 + (ky & 1);   // rrii group layout
    #pragma unroll
    for (int j = 0; j < 4; j++) {
        int kxp = grp*4 + j;
        float2 r = unpack2(Srp[j]);
        float2 im = unpack2(Sip[j]);
        So[(2*kxp)*64 + off]         = r.x*scl;
        So[(2*kxp + 1)*64 + off]     = r.y*scl;
        So[(2*kxp)*64 + off + 2]     = im.x*scl;
        So[(2*kxp + 1)*64 + off + 2] = im.y*scl;
    }
}

// ---------------- kC: per-mode channel mix; 4b x 4o tiles, 6-stage pipeline, 1 barrier ----------------
// smem: S 6 stages x 1024 floats, W 6 stages x 1024 floats
#define SS6(st,b,f)    sdyn[(st)*1024 + (b)*64 + (f)]
#define WS6(st,h,o,f)  sdyn[6144 + (st)*1024 + (h)*512 + (o)*32 + (f)]

__global__ void __launch_bounds__(256, 2) kC_mix6(const float* __restrict__ w_real,
                                                  const float* __restrict__ w_imag) {
    extern __shared__ float sdyn[];
    int t = threadIdx.x;
    int kx = blockIdx.x >> 4;
    int o0 = (blockIdx.x & 15) << 4;

    int sb = t >> 4, sf = t & 15;                       // S copy role
    const float* wsrc = (t < 128) ? w_real : w_imag;    // W copy role
    int whalf = t >> 7, wo = (t >> 3) & 15, wf = t & 7;

    int kyp = t & 15, bq = (t >> 4) & 3, oq = t >> 6;

    u64 ar[4][4], ai[4][4];
    #pragma unroll
    for (int b4 = 0; b4 < 4; b4++)
        #pragma unroll
        for (int o4 = 0; o4 < 4; o4++) { ar[b4][o4] = 0ULL; ai[b4][o4] = 0ULL; }

    const float* SmF = (const float*)g_Smode;

    // prologue: stages 0..4
    #pragma unroll
    for (int i = 0; i < 5; i++) {
        cpasync16(smem_u32(&SS6(i, sb, sf*4)), SmF + (size_t)(sb*CC + i)*2048 + kx*64 + sf*4);
        cpasync16(smem_u32(&WS6(i, whalf, wo, wf*4)),
                  wsrc + ((size_t)(i*CC + o0 + wo) << 10) + (kx << 5) + wf*4);
        cpcommit();
    }

    for (int i = 0; i < CC; i++) {
        cpwait<4>();          // stage i complete
        __syncthreads();      // all threads past iter i-1 (stage (i-1)%6 free)
        if (i + 5 < CC) {
            int ip = i + 5, st2 = (i + 5) % 6;
            cpasync16(smem_u32(&SS6(st2, sb, sf*4)), SmF + (size_t)(sb*CC + ip)*2048 + kx*64 + sf*4);
            cpasync16(smem_u32(&WS6(st2, whalf, wo, wf*4)),
                      wsrc + ((size_t)(ip*CC + o0 + wo) << 10) + (kx << 5) + wf*4);
        }
        cpcommit();
        int st = i % 6;
        u64 sx[4], sy[4], nsy[4];
        #pragma unroll
        for (int b4 = 0; b4 < 4; b4++) {
            int b = 4*b4 + bq;
            sx[b4]  = *(u64*)&SS6(st, b, 4*kyp);
            sy[b4]  = *(u64*)&SS6(st, b, 4*kyp + 2);
            nsy[b4] = neg2(sy[b4]);
        }
        #pragma unroll
        for (int o4 = 0; o4 < 4; o4++) {
            int ow = 4*o4 + oq;
            u64 wr = *(u64*)&WS6(st, 0, ow, 2*kyp);
            u64 wi = *(u64*)&WS6(st, 1, ow, 2*kyp);
            #pragma unroll
            for (int b4 = 0; b4 < 4; b4++) {
                ar[b4][o4] = fma2(sx[b4], wr, fma2(nsy[b4], wi, ar[b4][o4]));
                ai[b4][o4] = fma2(sx[b4], wi, fma2(sy[b4],  wr, ai[b4][o4]));
            }
        }
    }
    float* OmF = (float*)g_Omode;
    #pragma unroll
    for (int b4 = 0; b4 < 4; b4++) {
        int b = 4*b4 + bq;
        #pragma unroll
        for (int o4 = 0; o4 < 4; o4++) {
            int o = o0 + 4*o4 + oq;
            float* dst = OmF + (size_t)(b*CC + o)*2048 + kx*64;
            *(float2*)&dst[2*kyp]      = unpack2(ar[b4][o4]);
            *(float2*)&dst[32 + 2*kyp] = unpack2(ai[b4][o4]);
        }
    }
}

// ---------------- kD: inverse kx-DFT, packed f32x2 ----------------
__global__ void __launch_bounds__(256) kD_pack() {
    __shared__ float tabCT[32][128];
    __shared__ float tabST[32][128];
    __shared__ float sO[32][64];
    int t = threadIdx.x;
    int bo = blockIdx.x;
    for (int e = t; e < 4096; e += 256) {
        int kx = e >> 7, n = e & 127;
        float2 cs = g_tabJK[n*32 + kx];
        tabCT[kx][n] = cs.x;
        tabST[kx][n] = cs.y;
    }
    {
        const float4* src = (const float4*)((const float*)g_Omode + (size_t)bo*2048);
        #pragma unroll
        for (int q = 0; q < 2; q++) ((float4*)sO)[t + 256*q] = src[t + 256*q];
    }
    __syncthreads();

    int ky = t & 31, npg = t >> 5;
    u64 Grp[8], Gip[8];
    #pragma unroll
    for (int j = 0; j < 8; j++) { Grp[j] = 0ULL; Gip[j] = 0ULL; }

    for (int kx = 0; kx < MM; kx++) {
        float Or = sO[kx][ky], Oi = sO[kx][32 + ky];
        u64 Orr = pack2(Or, Or);
        u64 Oii = pack2(Oi, Oi);
        u64 nOii = pack2(-Oi, -Oi);
        #pragma unroll
        for (int j = 0; j < 8; j++) {
            int n0 = npg*16 + 2*j;
            u64 cp = *(u64*)&tabCT[kx][n0];
            u64 sp = *(u64*)&tabST[kx][n0];
            Grp[j] = fma2(Orr, cp, fma2(nOii, sp, Grp[j]));
            Gip[j] = fma2(Orr, sp, fma2(Oii,  cp, Gip[j]));
        }
    }
    float fac = (ky == 0 ? 1.f : 2.f) * (1.f/128.f);
    float* Ao = (float*)g_A + (size_t)bo*8192;
    #pragma unroll
    for (int j = 0; j < 8; j++) {
        int n0 = npg*16 + 2*j;
        float2 gr = unpack2(Grp[j]);
        float2 gi = unpack2(Gip[j]);
        *(float2*)&Ao[(size_t)n0*64 + 2*ky]       = make_float2(gr.x*fac, gi.x*fac);
        *(float2*)&Ao[(size_t)(n0 + 1)*64 + 2*ky] = make_float2(gr.y*fac, gi.y*fac);
    }
}

// ---------------- kE: inverse C2R along ky as tf32 GEMM ----------------
#define GSE_(r,k)   sdyn[(r)*68 + (k)]
#define USE_(k,n)   sdyn[8704 + (k)*132 + (n)]

__global__ void __launch_bounds__(256, 2) kE_mma() {
    extern __shared__ float sdyn[];
    int t = threadIdx.x, lane = t & 31, warp = t >> 5;
    int wm = warp >> 1, wn = warp & 1;
    int R0 = blockIdx.x * 128;

    for (int e = t; e < MM*HH; e += 256) {
        int ky = e >> 7, m = e & 127;
        float2 cs = g_tabKJ[e];
        USE_(2*ky,     m) = cs.x;
        USE_(2*ky + 1, m) = -cs.y;
    }
    const float* Gp = (const float*)g_A;
    #pragma unroll
    for (int q = 0; q < 8; q++) {
        int idx = t + 256*q;
        int row = idx >> 4, c4 = idx & 15;
        cpasync16(smem_u32(&GSE_(row, c4*4)), Gp + (size_t)(R0 + row)*64 + c4*4);
    }
    cpcommit();
    cpwait<0>();
    __syncthreads();

    float acc[2][8][4];
    #pragma unroll
    for (int mf = 0; mf < 2; mf++)
        #pragma unroll
        for (int nf = 0; nf < 8; nf++)
            #pragma unroll
            for (int e = 0; e < 4; e++) acc[mf][nf][e] = 0.f;

    #pragma unroll
    for (int k8 = 0; k8 < 8; k8++) {
        uint32_t a[2][4], b[8][2];
        int arow = wm*32 + (lane >> 2);
        int acol = (lane & 3) + k8*8;
        #pragma unroll
        for (int mf = 0; mf < 2; mf++) {
            int r = arow + mf*16;
            a[mf][0] = f2tf(GSE_(r,     acol));
            a[mf][1] = f2tf(GSE_(r + 8, acol));
            a[mf][2] = f2tf(GSE_(r,     acol + 4));
            a[mf][3] = f2tf(GSE_(r + 8, acol + 4));
        }
        int kg = k8*8 + (lane & 3);
        int bn0 = wn*64 + (lane >> 2);
        #pragma unroll
        for (int nf = 0; nf < 8; nf++) {
            b[nf][0] = f2tf(USE_(kg,     bn0 + nf*8));
            b[nf][1] = f2tf(USE_(kg + 4, bn0 + nf*8));
        }
        #pragma unroll
        for (int mf = 0; mf < 2; mf++)
            #pragma unroll
            for (int nf = 0; nf < 8; nf++)
                mma_tf32(acc[mf][nf], a[mf], b[nf]);
    }

    #pragma unroll
    for (int mf = 0; mf < 2; mf++) {
        int r = R0 + wm*32 + mf*16 + (lane >> 2);
        #pragma unroll
        for (int nf = 0; nf < 8; nf++) {
            int col = wn*64 + nf*8 + 2*(lane & 3);
            *(float2*)&g_h[(size_t)r*128 + col]       = make_float2(acc[mf][nf][0], acc[mf][nf][1]);
            *(float2*)&g_h[(size_t)(r + 8)*128 + col] = make_float2(acc[mf][nf][2], acc[mf][nf][3]);
        }
    }
}

// ---------------- kF: pointwise GEMM via tf32 mma + fused epilogue + GN stats ----------------
#define ASM_(st,r,c) sdyn[(st)*4608 + (r)*36 + (c)]
#define BSM_(st,k,n) sdyn[9216 + (st)*4352 + (k)*136 + (n)]

__global__ void __launch_bounds__(256, 2) kF_mma(const float* __restrict__ x,
                                                 const float* __restrict__ pw_w,
                                                 const float* __restrict__ pw_b) {
    extern __shared__ float sdyn[];
    int t = threadIdx.x;
    int lane = t & 31, warp = t >> 5;
    int wm = warp >> 1, wn = warp & 1;
    int bi = blockIdx.x;
    int bb = bi >> 8;
    int ot = (bi >> 7) & 1, hwt = bi & 127;
    int o0 = ot * 128, hw0 = hwt * 128;

    float acc[2][8][4];
    #pragma unroll
    for (int mf = 0; mf < 2; mf++)
        #pragma unroll
        for (int nf = 0; nf < 8; nf++)
            #pragma unroll
            for (int e = 0; e < 4; e++) acc[mf][nf][e] = 0.f;

    {
        int i0 = 0;
        #pragma unroll
        for (int q = 0; q < 4; q++) {
            int idx = t + 256*q;
            int row = idx >> 3, c4 = idx & 7;
            cpasync16(smem_u32(&ASM_(0, row, c4*4)), pw_w + (size_t)(o0 + row)*CC + i0 + c4*4);
        }
        #pragma unroll
        for (int q = 0; q < 4; q++) {
            int idx = t + 256*q;
            int row = idx >> 5, c4 = idx & 31;
            cpasync16(smem_u32(&BSM_(0, row, c4*4)),
                      x + (((size_t)(bb*CC + i0 + row)) << 14) + hw0 + c4*4);
        }
        cpcommit();
    }

    for (int kc = 0; kc < 8; kc++) {
        if (kc + 1 < 8) {
            int i0 = (kc + 1) * 32, st2 = (kc + 1) & 1;
            #pragma unroll
            for (int q = 0; q < 4; q++) {
                int idx = t + 256*q;
                int row = idx >> 3, c4 = idx & 7;
                cpasync16(smem_u32(&ASM_(st2, row, c4*4)), pw_w + (size_t)(o0 + row)*CC + i0 + c4*4);
            }
            #pragma unroll
            for (int q = 0; q < 4; q++) {
                int idx = t + 256*q;
                int row = idx >> 5, c4 = idx & 31;
                cpasync16(smem_u32(&BSM_(st2, row, c4*4)),
                          x + (((size_t)(bb*CC + i0 + row)) << 14) + hw0 + c4*4);
            }
            cpcommit();
            cpwait<1>();
        } else {
            cpwait<0>();
        }
        __syncthreads();
        int st = kc & 1;
        #pragma unroll
        for (int k8 = 0; k8 < 4; k8++) {
            uint32_t a[2][4], b[8][2];
            int arow = wm*32 + (lane >> 2);
            int acol = (lane & 3) + k8*8;
            #pragma unroll
            for (int mf = 0; mf < 2; mf++) {
                int r = arow + mf*16;
                a[mf][0] = f2tf(ASM_(st, r,     acol));
                a[mf][1] = f2tf(ASM_(st, r + 8, acol));
                a[mf][2] = f2tf(ASM_(st, r,     acol + 4));
                a[mf][3] = f2tf(ASM_(st, r + 8, acol + 4));
            }
            int bk = (lane & 3) + k8*8;
            int bn0 = wn*64 + (lane >> 2);
            #pragma unroll
            for (int nf = 0; nf < 8; nf++) {
                b[nf][0] = f2tf(BSM_(st, bk,     bn0 + nf*8));
                b[nf][1] = f2tf(BSM_(st, bk + 4, bn0 + nf*8));
            }
            #pragma unroll
            for (int mf = 0; mf < 2; mf++)
                #pragma unroll
                for (int nf = 0; nf < 8; nf++)
                    mma_tf32(acc[mf][nf], a[mf], b[nf]);
        }
        __syncthreads();
    }

    float lsum = 0.f, lsum2 = 0.f;
    #pragma unroll
    for (int mf = 0; mf < 2; mf++) {
        int rbase = o0 + wm*32 + mf*16 + (lane >> 2);
        float addb[2], scl[2], shf[2];
        #pragma unroll
        for (int h = 0; h < 2; h++) {
            int o = rbase + 8*h;
            addb[h] = pw_b[o] + g_tvec[bb*CC + o];
            scl[h]  = 1.f + g_scale[bb*CC + o];
            shf[h]  = g_shift[bb*CC + o];
        }
        #pragma unroll
        for (int nf = 0; nf < 8; nf++) {
            int col = hw0 + wn*64 + nf*8 + 2*(lane & 3);
            #pragma unroll
            for (int h = 0; h < 2; h++) {
                size_t idx = (((size_t)(bb*CC + rbase + 8*h)) << 14) + col;
                float2 hv = *(float2*)&g_h[idx];
                float v0 = (acc[mf][nf][2*h]     + hv.x + addb[h]) * scl[h] + shf[h];
                float v1 = (acc[mf][nf][2*h + 1] + hv.y + addb[h]) * scl[h] + shf[h];
                *(float2*)&g_h[idx] = make_float2(v0, v1);
                lsum  += v0 + v1;
                lsum2 += v0*v0 + v1*v1;
            }
        }
    }
    #pragma unroll
    for (int off = 16; off; off >>= 1) {
        lsum  += __shfl_xor_sync(0xffffffffu, lsum, off);
        lsum2 += __shfl_xor_sync(0xffffffffu, lsum2, off);
    }
    if (lane == 0) {
        int g = (o0 + wm*32) >> 5;
        atomicAdd(&g_stats[(bb*NG + g)*2],     lsum);
        atomicAdd(&g_stats[(bb*NG + g)*2 + 1], lsum2);
    }
}

// ---------------- kG ----------------
__global__ void kG_stats() {
    int t = threadIdx.x;
    if (t < BB*NG) {
        float s = g_stats[t*2], s2 = g_stats[t*2 + 1];
        const float inv = 1.f / 524288.f;
        float mu = s * inv;
        float var = s2 * inv - mu*mu;
        g_stats[t*2]     = mu;
        g_stats[t*2 + 1] = rsqrtf(var + EPSV);
    }
}

// ---------------- kH ----------------
__device__ __forceinline__ float gelu_res(float h, float xr, float ga, float be) {
    float hn = fmaf(h, ga, be);
    return xr + 0.5f*hn*(1.f + erff(hn*0.70710678118654752f));
}

__global__ void __launch_bounds__(256) kH_final(const float* __restrict__ x,
                                                const float* __restrict__ gn_g,
                                                const float* __restrict__ gn_b,
                                                float* __restrict__ out) {
    int idx4 = blockIdx.x*256 + threadIdx.x;
    int base = idx4 << 2;
    int c = (base >> 14) & 255;
    int b = base >> 22;
    int g = c >> 5;
    float mu = g_stats[(b*NG + g)*2];
    float rs = g_stats[(b*NG + g)*2 + 1];
    float ga = gn_g[c] * rs;
    float be = gn_b[c] - mu * ga;
    float4 hv = ((const float4*)g_h)[idx4];
    float4 xv = ((const float4*)x)[idx4];
    float4 r;
    r.x = gelu_res(hv.x, xv.x, ga, be);
    r.y = gelu_res(hv.y, xv.y, ga, be);
    r.z = gelu_res(hv.z, xv.z, ga, be);
    r.w = gelu_res(hv.w, xv.w, ga, be);
    ((float4*)out)[idx4] = r;
}

extern "C" void kernel_launch(void* const* d_in, const int* in_sizes, int n_in,
                              void* d_out, int out_size) {
    const float* x        = (const float*)d_in[0];
    const float* t_emb    = (const float*)d_in[1];
    const float* cond_emb = (const float*)d_in[2];
    const float* w_real   = (const float*)d_in[3];
    const float* w_imag   = (const float*)d_in[4];
    const float* pw_w     = (const float*)d_in[5];
    const float* pw_b     = (const float*)d_in[6];
    const float* tp_w     = (const float*)d_in[7];
    const float* tp_b     = (const float*)d_in[8];
    const float* cp_w     = (const float*)d_in[9];
    const float* cp_b     = (const float*)d_in[10];
    const float* gn_g     = (const float*)d_in[11];
    const float* gn_b     = (const float*)d_in[12];
    float* out = (float*)d_out;

    static int smem_set = 0;
    if (!smem_set) {
        cudaFuncSetAttribute(kF_mma, cudaFuncAttributeMaxDynamicSharedMemorySize, 73728);
        cudaFuncSetAttribute(kA_mma, cudaFuncAttributeMaxDynamicSharedMemorySize, 71680);
        cudaFuncSetAttribute(kE_mma, cudaFuncAttributeMaxDynamicSharedMemorySize, 68608);
        cudaFuncSetAttribute(kB_pack, cudaFuncAttributeMaxDynamicSharedMemorySize, 98304);
        cudaFuncSetAttribute(kC_mix6, cudaFuncAttributeMaxDynamicSharedMemorySize, 49152);
        smem_set = 1;
    }

    k0_prep<<<BB + 1, 256>>>(t_emb, cond_emb, tp_w, tp_b, cp_w, cp_b);
    kA_mma<<<4096, 256, 71680>>>(x);
    kB_pack<<<2048, 256, 98304>>>();
    kC_mix6<<<512, 256, 49152>>>(w_real, w_imag);
    kD_pack<<<4096, 256>>>();
    kE_mma<<<4096, 256, 68608>>>();
    kF_mma<<<4096, 256, 73728>>>(x, pw_w, pw_b);
    kG_stats<<<1, 256>>>();
    kH_final<<<65536, 256>>>(x, gn_g, gn_b, out);
}

// round 8
// speedup vs baseline: 2.0084x; 1.0822x over previous
#include <cuda_runtime.h>
#include <cstdint>
#include <math.h>

#define BB 16
#define CC 256
#define HH 128
#define WW 128
#define HW 16384
#define MM 32
#define NMODE 1024
#define TD 512
#define CD 512
#define NG 8
#define EPSV 1e-5f

typedef unsigned long long u64;

// ---------------- persistent scratch ----------------
__device__ float2 g_A[(size_t)BB*CC*HH*MM];
__device__ float2 g_Smode[(size_t)BB*CC*NMODE];  // SoA per kx: 64 floats = 16 groups (r,r,i,i)
__device__ float2 g_Omode[(size_t)BB*CC*NMODE];  // SoA per kx: 32 real + 32 imag
__device__ float  g_h[(size_t)BB*CC*HW];
__device__ float  g_tvec[BB*CC];
__device__ float  g_scale[BB*CC];
__device__ float  g_shift[BB*CC];
__device__ float  g_stats[BB*NG*2];
__device__ float2 g_tabJK[HH*MM];
__device__ float2 g_tabKJ[MM*HH];

// ---------------- helpers ----------------
__device__ __forceinline__ uint32_t smem_u32(const void* p) {
    return (uint32_t)__cvta_generic_to_shared(p);
}
__device__ __forceinline__ void cpasync16(uint32_t dst, const void* src) {
    asm volatile("cp.async.ca.shared.global [%0], [%1], 16;" :: "r"(dst), "l"(src));
}
__device__ __forceinline__ void cpcommit() { asm volatile("cp.async.commit_group;"); }
template<int N>
__device__ __forceinline__ void cpwait() { asm volatile("cp.async.wait_group %0;" :: "n"(N)); }
__device__ __forceinline__ uint32_t f2tf(float v) {
    uint32_t r;
    asm("cvt.rna.tf32.f32 %0, %1;" : "=r"(r) : "f"(v));
    return r;
}
__device__ __forceinline__ void mma_tf32(float* d, const uint32_t* a, const uint32_t* b) {
    asm volatile("mma.sync.aligned.m16n8k8.row.col.f32.tf32.tf32.f32 "
                 "{%0,%1,%2,%3}, {%4,%5,%6,%7}, {%8,%9}, {%0,%1,%2,%3};"
                 : "+f"(d[0]), "+f"(d[1]), "+f"(d[2]), "+f"(d[3])
                 : "r"(a[0]), "r"(a[1]), "r"(a[2]), "r"(a[3]), "r"(b[0]), "r"(b[1]));
}
__device__ __forceinline__ u64 pack2(float x, float y) {
    u64 r; asm("mov.b64 %0, {%1, %2};" : "=l"(r) : "f"(x), "f"(y)); return r;
}
__device__ __forceinline__ u64 fma2(u64 a, u64 b, u64 c) {
    u64 d; asm("fma.rn.f32x2 %0, %1, %2, %3;" : "=l"(d) : "l"(a), "l"(b), "l"(c)); return d;
}
__device__ __forceinline__ u64 neg2(u64 a) { return a ^ 0x8000000080000000ULL; }
__device__ __forceinline__ float2 unpack2(u64 a) {
    float2 v; asm("mov.b64 {%0, %1}, %2;" : "=f"(v.x), "=f"(v.y) : "l"(a)); return v;
}

// ---------------- K0 ----------------
__global__ void k0_prep(const float* __restrict__ t_emb, const float* __restrict__ cond_emb,
                        const float* __restrict__ tp_w, const float* __restrict__ tp_b,
                        const float* __restrict__ cp_w, const float* __restrict__ cp_b) {
    int t = threadIdx.x;
    if (blockIdx.x == BB) {
        for (int e = t; e < HH*MM; e += 256) {
            int j = e >> 5, k = e & 31;
            float ang = (float)((j * k) & 127) * 0.049087385212340517f;
            float s, c; sincosf(ang, &s, &c);
            g_tabJK[j*MM + k] = make_float2(c, s);
            g_tabKJ[k*HH + j] = make_float2(c, s);
        }
        if (t < BB*NG*2) g_stats[t] = 0.f;
        return;
    }
    int b = blockIdx.x;
    __shared__ float st[TD];
    __shared__ float sc[CD];
    for (int e = t; e < TD; e += 256) { float v = t_emb[b*TD + e];   st[e] = v / (1.f + expf(-v)); }
    for (int e = t; e < CD; e += 256) { float v = cond_emb[b*CD + e]; sc[e] = v / (1.f + expf(-v)); }
    __syncthreads();
    int c = t;
    float tv = tp_b[c], s1 = cp_b[c], s2 = cp_b[c + CC];
    const float* tw = tp_w + (size_t)c*TD;
    const float* c1 = cp_w + (size_t)c*CD;
    const float* c2 = cp_w + (size_t)(c + CC)*CD;
    for (int d = 0; d < TD; d++) tv = fmaf(st[d], tw[d], tv);
    for (int d = 0; d < CD; d++) { s1 = fmaf(sc[d], c1[d], s1); s2 = fmaf(sc[d], c2[d], s2); }
    g_tvec[b*CC + c] = tv;
    g_scale[b*CC + c] = s1;
    g_shift[b*CC + c] = s2;
}

// ---------------- kA: forward ky-DFT as tf32 GEMM ----------------
#define TSA_(k,n)      sdyn[(k)*68 + (n)]
#define XSA_(st,r,k)   sdyn[8704 + (st)*4608 + (r)*36 + (k)]

__global__ void __launch_bounds__(256, 2) kA_mma(const float* __restrict__ x) {
    extern __shared__ float sdyn[];
    int t = threadIdx.x, lane = t & 31, warp = t >> 5;
    int wm = warp >> 1, wn = warp & 1;
    int R0 = blockIdx.x * 128;

    for (int e = t; e < HH*MM; e += 256) {
        int m = e >> 5, ky = e & 31;
        float2 cs = g_tabJK[e];
        TSA_(m, 2*ky)     = cs.x;
        TSA_(m, 2*ky + 1) = -cs.y;
    }
    #pragma unroll
    for (int q = 0; q < 4; q++) {
        int idx = t + 256*q;
        int row = idx >> 3, c4 = idx & 7;
        cpasync16(smem_u32(&XSA_(0, row, c4*4)), x + (size_t)(R0 + row)*128 + c4*4);
    }
    cpcommit();

    float acc[2][4][4];
    #pragma unroll
    for (int mf = 0; mf < 2; mf++)
        #pragma unroll
        for (int nf = 0; nf < 4; nf++)
            #pragma unroll
            for (int e = 0; e < 4; e++) acc[mf][nf][e] = 0.f;

    for (int kc = 0; kc < 4; kc++) {
        if (kc + 1 < 4) {
            int k0 = (kc + 1) * 32, st2 = (kc + 1) & 1;
            #pragma unroll
            for (int q = 0; q < 4; q++) {
                int idx = t + 256*q;
                int row = idx >> 3, c4 = idx & 7;
                cpasync16(smem_u32(&XSA_(st2, row, c4*4)), x + (size_t)(R0 + row)*128 + k0 + c4*4);
            }
            cpcommit();
            cpwait<1>();
        } else {
            cpwait<0>();
        }
        __syncthreads();
        int st = kc & 1;
        #pragma unroll
        for (int k8 = 0; k8 < 4; k8++) {
            uint32_t a[2][4], b[4][2];
            int arow = wm*32 + (lane >> 2);
            int acol = (lane & 3) + k8*8;
            #pragma unroll
            for (int mf = 0; mf < 2; mf++) {
                int r = arow + mf*16;
                a[mf][0] = f2tf(XSA_(st, r,     acol));
                a[mf][1] = f2tf(XSA_(st, r + 8, acol));
                a[mf][2] = f2tf(XSA_(st, r,     acol + 4));
                a[mf][3] = f2tf(XSA_(st, r + 8, acol + 4));
            }
            int kg = kc*32 + k8*8 + (lane & 3);
            int bn0 = wn*32 + (lane >> 2);
            #pragma unroll
            for (int nf = 0; nf < 4; nf++) {
                b[nf][0] = f2tf(TSA_(kg,     bn0 + nf*8));
                b[nf][1] = f2tf(TSA_(kg + 4, bn0 + nf*8));
            }
            #pragma unroll
            for (int mf = 0; mf < 2; mf++)
                #pragma unroll
                for (int nf = 0; nf < 4; nf++)
                    mma_tf32(acc[mf][nf], a[mf], b[nf]);
        }
        __syncthreads();
    }
    float* Ao = (float*)g_A;
    #pragma unroll
    for (int mf = 0; mf < 2; mf++) {
        int r = R0 + wm*32 + mf*16 + (lane >> 2);
        #pragma unroll
        for (int nf = 0; nf < 4; nf++) {
            int col = wn*32 + nf*8 + 2*(lane & 3);
            *(float2*)&Ao[(size_t)r*64 + col]       = make_float2(acc[mf][nf][0], acc[mf][nf][1]);
            *(float2*)&Ao[(size_t)(r + 8)*64 + col] = make_float2(acc[mf][nf][2], acc[mf][nf][3]);
        }
    }
}

// ---------------- kB: forward DFT along h, packed f32x2; rrii-group output ----------------
#define TCB_(n,kx)    dynB[(n)*32 + (kx)]
#define TSB_(n,kx)    dynB[4096 + (n)*32 + (kx)]
#define SAB_(sl,n,c)  dynB[8192 + (sl)*8192 + (n)*64 + (c)]

__global__ void __launch_bounds__(256, 2) kB_pack() {
    extern __shared__ float dynB[];
    int t = threadIdx.x;
    int bc0 = blockIdx.x * 2;
    for (int e = t; e < 4096; e += 256) {
        float2 cs = g_tabJK[e];       // e = n*32 + kx
        TCB_(e >> 5, e & 31) = cs.x;
        TSB_(e >> 5, e & 31) = cs.y;
    }
    {
        const float4* src = (const float4*)((const float*)g_A + (size_t)bc0*8192);
        float4* dst = (float4*)&dynB[8192];
        #pragma unroll
        for (int q = 0; q < 16; q++) dst[t + 256*q] = src[t + 256*q];
    }
    __syncthreads();

    int sl = t >> 7, u = t & 127;
    int ky = u & 31, grp = u >> 5;
    u64 Srp[4], Sip[4];
    #pragma unroll
    for (int j = 0; j < 4; j++) { Srp[j] = 0ULL; Sip[j] = 0ULL; }

    for (int n = 0; n < HH; n++) {
        float2 a = *(float2*)&SAB_(sl, n, 2*ky);
        u64 arr = pack2(a.x, a.x);
        u64 aii = pack2(a.y, a.y);
        u64 nar = pack2(-a.x, -a.x);
        #pragma unroll
        for (int j = 0; j < 4; j++) {
            int kxp = grp*4 + j;
            u64 cp = *(u64*)&TCB_(n, 2*kxp);
            u64 sp = *(u64*)&TSB_(n, 2*kxp);
            Srp[j] = fma2(arr, cp, fma2(aii, sp, Srp[j]));
            Sip[j] = fma2(aii, cp, fma2(nar, sp, Sip[j]));
        }
    }
    const float scl = 1.f/128.f;
    float* So = (float*)g_Smode + (size_t)(bc0 + sl)*2048;
    int off = (ky >> 1)*4 + (ky & 1);   // rrii group layout
    #pragma unroll
    for (int j = 0; j < 4; j++) {
        int kxp = grp*4 + j;
        float2 r = unpack2(Srp[j]);
        float2 im = unpack2(Sip[j]);
        So[(2*kxp)*64 + off]         = r.x*scl;
        So[(2*kxp + 1)*64 + off]     = r.y*scl;
        So[(2*kxp)*64 + off + 2]     = im.x*scl;
        So[(2*kxp + 1)*64 + off + 2] = im.y*scl;
    }
}

// ---------------- kC: per-mode channel mix; 4b x 4o tiles, 6-stage pipeline, 1 barrier ----------------
#define SS6(st,b,f)    sdyn[(st) + (b)*64 + (f)]
#define WS6(st,h,o,f)  sdyn[6144 + (st) + (h)*512 + (o)*32 + (f)]

__global__ void __launch_bounds__(256, 2) kC_mix6(const float* __restrict__ w_real,
                                                  const float* __restrict__ w_imag) {
    extern __shared__ float sdyn[];
    int t = threadIdx.x;
    int kx = blockIdx.x >> 4;
    int o0 = (blockIdx.x & 15) << 4;

    int sb = t >> 4, sf = t & 15;                       // S copy role
    const float* wsrc = (t < 128) ? w_real : w_imag;    // W copy role
    int whalf = t >> 7, wo = (t >> 3) & 15, wf = t & 7;

    int kyp = t & 15, bq = (t >> 4) & 3, oq = t >> 6;

    u64 ar[4][4], ai[4][4];
    #pragma unroll
    for (int b4 = 0; b4 < 4; b4++)
        #pragma unroll
        for (int o4 = 0; o4 < 4; o4++) { ar[b4][o4] = 0ULL; ai[b4][o4] = 0ULL; }

    // strength-reduced streaming pointers (advance per channel i)
    const float* sPtr = (const float*)g_Smode + (size_t)(sb*CC)*2048 + kx*64 + sf*4;
    const float* wPtr = wsrc + ((size_t)(o0 + wo) << 10) + (kx << 5) + wf*4;
    uint32_t sDst = smem_u32(&SS6(0, sb, sf*4));
    uint32_t wDst = smem_u32(&WS6(0, whalf, wo, wf*4));

    // prologue: stages 0..4
    #pragma unroll
    for (int i = 0; i < 5; i++) {
        cpasync16(sDst + i*4096, sPtr);  sPtr += 2048;
        cpasync16(wDst + i*4096, wPtr);  wPtr += (size_t)CC << 10;
        cpcommit();
    }

    int stc = 0;          // compute stage byte/float offset (x1024 floats -> track in floats)
    int stp = 5*1024;     // prefetch stage offset in floats
    uint32_t sPD = sDst + 5*4096, wPD = wDst + 5*4096;  // prefetch smem dsts

    for (int i = 0; i < CC; i++) {
        cpwait<4>();
        __syncthreads();
        if (i + 5 < CC) {
            cpasync16(sPD, sPtr);  sPtr += 2048;
            cpasync16(wPD, wPtr);  wPtr += (size_t)CC << 10;
        }
        cpcommit();
        sPD += 4096; wPD += 4096;
        if (stp == 5*1024) { sPD -= 6*4096; wPD -= 6*4096; stp = 0; } else stp += 1024;

        int st = stc;
        u64 sx[4], sy[4], nsy[4];
        #pragma unroll
        for (int b4 = 0; b4 < 4; b4++) {
            int b = 4*b4 + bq;
            sx[b4]  = *(u64*)&SS6(st, b, 4*kyp);
            sy[b4]  = *(u64*)&SS6(st, b, 4*kyp + 2);
            nsy[b4] = neg2(sy[b4]);
        }
        #pragma unroll
        for (int o4 = 0; o4 < 4; o4++) {
            int ow = 4*o4 + oq;
            u64 wr = *(u64*)&WS6(st, 0, ow, 2*kyp);
            u64 wi = *(u64*)&WS6(st, 1, ow, 2*kyp);
            #pragma unroll
            for (int b4 = 0; b4 < 4; b4++) {
                ar[b4][o4] = fma2(sx[b4], wr, fma2(nsy[b4], wi, ar[b4][o4]));
                ai[b4][o4] = fma2(sx[b4], wi, fma2(sy[b4],  wr, ai[b4][o4]));
            }
        }
        stc = (stc == 5*1024) ? 0 : stc + 1024;
    }
    float* OmF = (float*)g_Omode;
    #pragma unroll
    for (int b4 = 0; b4 < 4; b4++) {
        int b = 4*b4 + bq;
        #pragma unroll
        for (int o4 = 0; o4 < 4; o4++) {
            int o = o0 + 4*o4 + oq;
            float* dst = OmF + (size_t)(b*CC + o)*2048 + kx*64;
            *(float2*)&dst[2*kyp]      = unpack2(ar[b4][o4]);
            *(float2*)&dst[32 + 2*kyp] = unpack2(ai[b4][o4]);
        }
    }
}

// ---------------- kDE: fused inverse kx-DFT (fp32x2, in smem) + inverse C2R ky (tf32 mma) ----------------
// smem: GSE [128][68] @0 (8704), USE [64][132] @8704 (8448), SO [32][64] @17152 (2048) = 19200 floats
#define GSE_(r,k)   sdyn[(r)*68 + (k)]
#define USE_(k,n)   sdyn[8704 + (k)*132 + (n)]
#define SOD_(kx,f)  sdyn[17152 + (kx)*64 + (f)]

__global__ void __launch_bounds__(256, 2) kDE_fused() {
    extern __shared__ float sdyn[];
    int t = threadIdx.x, lane = t & 31, warp = t >> 5;
    int wm = warp >> 1, wn = warp & 1;
    int bo = blockIdx.x;

    // USE table: [2ky][m]=cos, [2ky+1][m]=-sin  (doubles as kD's [2kx][n] table)
    for (int e = t; e < MM*HH; e += 256) {
        int ky = e >> 7, m = e & 127;
        float2 cs = g_tabKJ[e];
        USE_(2*ky,     m) = cs.x;
        USE_(2*ky + 1, m) = -cs.y;
    }
    // load O modes for this (b,o)
    {
        const float4* src = (const float4*)((const float*)g_Omode + (size_t)bo*2048);
        ((float4*)&SOD_(0,0))[t]       = src[t];
        ((float4*)&SOD_(0,0))[t + 256] = src[t + 256];
    }
    __syncthreads();

    // ---- phase 1: kD (kx -> n), packed f32x2, writes GSE rows [n][2ky interleaved] ----
    {
        int ky = t & 31, npg = t >> 5;
        u64 Grp[8], Gip[8];
        #pragma unroll
        for (int j = 0; j < 8; j++) { Grp[j] = 0ULL; Gip[j] = 0ULL; }
        for (int kx = 0; kx < MM; kx++) {
            float Or = SOD_(kx, ky), Oi = SOD_(kx, 32 + ky);
            u64 Orr  = pack2(Or, Or);
            u64 Oii  = pack2(Oi, Oi);
            u64 nOrr = pack2(-Or, -Or);
            #pragma unroll
            for (int j = 0; j < 8; j++) {
                int n0 = npg*16 + 2*j;
                u64 cp  = *(u64*)&USE_(2*kx,     n0);   // cos
                u64 spn = *(u64*)&USE_(2*kx + 1, n0);   // -sin
                // Gr = Or*c + Oi*(-(-sin))... : Gr = Or*c - Oi*s = Or*c + Oi*spn? spn=-s -> Oi*spn = -Oi*s ✓
                Grp[j] = fma2(Orr, cp, fma2(Oii, spn, Grp[j]));
                // Gi = Or*s + Oi*c = -Or*spn + Oi*c
                Gip[j] = fma2(nOrr, spn, fma2(Oii, cp, Gip[j]));
            }
        }
        float fac = (ky == 0 ? 1.f : 2.f) * (1.f/128.f);
        #pragma unroll
        for (int j = 0; j < 8; j++) {
            int n0 = npg*16 + 2*j;
            float2 gr = unpack2(Grp[j]);
            float2 gi = unpack2(Gip[j]);
            *(float2*)&GSE_(n0,     2*ky) = make_float2(gr.x*fac, gi.x*fac);
            *(float2*)&GSE_(n0 + 1, 2*ky) = make_float2(gr.y*fac, gi.y*fac);
        }
    }
    __syncthreads();

    // ---- phase 2: kE tf32 mma, G[128x64] @ U[64x128] -> g_h rows ----
    float acc[2][8][4];
    #pragma unroll
    for (int mf = 0; mf < 2; mf++)
        #pragma unroll
        for (int nf = 0; nf < 8; nf++)
            #pragma unroll
            for (int e = 0; e < 4; e++) acc[mf][nf][e] = 0.f;

    #pragma unroll
    for (int k8 = 0; k8 < 8; k8++) {
        uint32_t a[2][4], b[8][2];
        int arow = wm*32 + (lane >> 2);
        int acol = (lane & 3) + k8*8;
        #pragma unroll
        for (int mf = 0; mf < 2; mf++) {
            int r = arow + mf*16;
            a[mf][0] = f2tf(GSE_(r,     acol));
            a[mf][1] = f2tf(GSE_(r + 8, acol));
            a[mf][2] = f2tf(GSE_(r,     acol + 4));
            a[mf][3] = f2tf(GSE_(r + 8, acol + 4));
        }
        int kg = k8*8 + (lane & 3);
        int bn0 = wn*64 + (lane >> 2);
        #pragma unroll
        for (int nf = 0; nf < 8; nf++) {
            b[nf][0] = f2tf(USE_(kg,     bn0 + nf*8));
            b[nf][1] = f2tf(USE_(kg + 4, bn0 + nf*8));
        }
        #pragma unroll
        for (int mf = 0; mf < 2; mf++)
            #pragma unroll
            for (int nf = 0; nf < 8; nf++)
                mma_tf32(acc[mf][nf], a[mf], b[nf]);
    }

    #pragma unroll
    for (int mf = 0; mf < 2; mf++) {
        int r = bo*128 + wm*32 + mf*16 + (lane >> 2);
        #pragma unroll
        for (int nf = 0; nf < 8; nf++) {
            int col = wn*64 + nf*8 + 2*(lane & 3);
            *(float2*)&g_h[(size_t)r*128 + col]       = make_float2(acc[mf][nf][0], acc[mf][nf][1]);
            *(float2*)&g_h[(size_t)(r + 8)*128 + col] = make_float2(acc[mf][nf][2], acc[mf][nf][3]);
        }
    }
}

// ---------------- kF: pointwise GEMM via tf32 mma + fused epilogue + GN stats ----------------
#define ASM_(st,r,c) sdyn[(st)*4608 + (r)*36 + (c)]
#define BSM_(st,k,n) sdyn[9216 + (st)*4352 + (k)*136 + (n)]

__global__ void __launch_bounds__(256, 2) kF_mma(const float* __restrict__ x,
                                                 const float* __restrict__ pw_w,
                                                 const float* __restrict__ pw_b) {
    extern __shared__ float sdyn[];
    int t = threadIdx.x;
    int lane = t & 31, warp = t >> 5;
    int wm = warp >> 1, wn = warp & 1;
    int bi = blockIdx.x;
    int bb = bi >> 8;
    int ot = (bi >> 7) & 1, hwt = bi & 127;
    int o0 = ot * 128, hw0 = hwt * 128;

    float acc[2][8][4];
    #pragma unroll
    for (int mf = 0; mf < 2; mf++)
        #pragma unroll
        for (int nf = 0; nf < 8; nf++)
            #pragma unroll
            for (int e = 0; e < 4; e++) acc[mf][nf][e] = 0.f;

    {
        int i0 = 0;
        #pragma unroll
        for (int q = 0; q < 4; q++) {
            int idx = t + 256*q;
            int row = idx >> 3, c4 = idx & 7;
            cpasync16(smem_u32(&ASM_(0, row, c4*4)), pw_w + (size_t)(o0 + row)*CC + i0 + c4*4);
        }
        #pragma unroll
        for (int q = 0; q < 4; q++) {
            int idx = t + 256*q;
            int row = idx >> 5, c4 = idx & 31;
            cpasync16(smem_u32(&BSM_(0, row, c4*4)),
                      x + (((size_t)(bb*CC + i0 + row)) << 14) + hw0 + c4*4);
        }
        cpcommit();
    }

    for (int kc = 0; kc < 8; kc++) {
        if (kc + 1 < 8) {
            int i0 = (kc + 1) * 32, st2 = (kc + 1) & 1;
            #pragma unroll
            for (int q = 0; q < 4; q++) {
                int idx = t + 256*q;
                int row = idx >> 3, c4 = idx & 7;
                cpasync16(smem_u32(&ASM_(st2, row, c4*4)), pw_w + (size_t)(o0 + row)*CC + i0 + c4*4);
            }
            #pragma unroll
            for (int q = 0; q < 4; q++) {
                int idx = t + 256*q;
                int row = idx >> 5, c4 = idx & 31;
                cpasync16(smem_u32(&BSM_(st2, row, c4*4)),
                          x + (((size_t)(bb*CC + i0 + row)) << 14) + hw0 + c4*4);
            }
            cpcommit();
            cpwait<1>();
        } else {
            cpwait<0>();
        }
        __syncthreads();
        int st = kc & 1;
        #pragma unroll
        for (int k8 = 0; k8 < 4; k8++) {
            uint32_t a[2][4], b[8][2];
            int arow = wm*32 + (lane >> 2);
            int acol = (lane & 3) + k8*8;
            #pragma unroll
            for (int mf = 0; mf < 2; mf++) {
                int r = arow + mf*16;
                a[mf][0] = f2tf(ASM_(st, r,     acol));
                a[mf][1] = f2tf(ASM_(st, r + 8, acol));
                a[mf][2] = f2tf(ASM_(st, r,     acol + 4));
                a[mf][3] = f2tf(ASM_(st, r + 8, acol + 4));
            }
            int bk = (lane & 3) + k8*8;
            int bn0 = wn*64 + (lane >> 2);
            #pragma unroll
            for (int nf = 0; nf < 8; nf++) {
                b[nf][0] = f2tf(BSM_(st, bk,     bn0 + nf*8));
                b[nf][1] = f2tf(BSM_(st, bk + 4, bn0 + nf*8));
            }
            #pragma unroll
            for (int mf = 0; mf < 2; mf++)
                #pragma unroll
                for (int nf = 0; nf < 8; nf++)
                    mma_tf32(acc[mf][nf], a[mf], b[nf]);
        }
        __syncthreads();
    }

    float lsum = 0.f, lsum2 = 0.f;
    #pragma unroll
    for (int mf = 0; mf < 2; mf++) {
        int rbase = o0 + wm*32 + mf*16 + (lane >> 2);
        float addb[2], scl[2], shf[2];
        #pragma unroll
        for (int h = 0; h < 2; h++) {
            int o = rbase + 8*h;
            addb[h] = pw_b[o] + g_tvec[bb*CC + o];
            scl[h]  = 1.f + g_scale[bb*CC + o];
            shf[h]  = g_shift[bb*CC + o];
        }
        #pragma unroll
        for (int nf = 0; nf < 8; nf++) {
            int col = hw0 + wn*64 + nf*8 + 2*(lane & 3);
            #pragma unroll
            for (int h = 0; h < 2; h++) {
                size_t idx = (((size_t)(bb*CC + rbase + 8*h)) << 14) + col;
                float2 hv = *(float2*)&g_h[idx];
                float v0 = (acc[mf][nf][2*h]     + hv.x + addb[h]) * scl[h] + shf[h];
                float v1 = (acc[mf][nf][2*h + 1] + hv.y + addb[h]) * scl[h] + shf[h];
                *(float2*)&g_h[idx] = make_float2(v0, v1);
                lsum  += v0 + v1;
                lsum2 += v0*v0 + v1*v1;
            }
        }
    }
    #pragma unroll
    for (int off = 16; off; off >>= 1) {
        lsum  += __shfl_xor_sync(0xffffffffu, lsum, off);
        lsum2 += __shfl_xor_sync(0xffffffffu, lsum2, off);
    }
    if (lane == 0) {
        int g = (o0 + wm*32) >> 5;
        atomicAdd(&g_stats[(bb*NG + g)*2],     lsum);
        atomicAdd(&g_stats[(bb*NG + g)*2 + 1], lsum2);
    }
}

// ---------------- kG ----------------
__global__ void kG_stats() {
    int t = threadIdx.x;
    if (t < BB*NG) {
        float s = g_stats[t*2], s2 = g_stats[t*2 + 1];
        const float inv = 1.f / 524288.f;
        float mu = s * inv;
        float var = s2 * inv - mu*mu;
        g_stats[t*2]     = mu;
        g_stats[t*2 + 1] = rsqrtf(var + EPSV);
    }
}

// ---------------- kH ----------------
__device__ __forceinline__ float gelu_res(float h, float xr, float ga, float be) {
    float hn = fmaf(h, ga, be);
    return xr + 0.5f*hn*(1.f + erff(hn*0.70710678118654752f));
}

__global__ void __launch_bounds__(256) kH_final(const float* __restrict__ x,
                                                const float* __restrict__ gn_g,
                                                const float* __restrict__ gn_b,
                                                float* __restrict__ out) {
    int idx4 = blockIdx.x*256 + threadIdx.x;
    int base = idx4 << 2;
    int c = (base >> 14) & 255;
    int b = base >> 22;
    int g = c >> 5;
    float mu = g_stats[(b*NG + g)*2];
    float rs = g_stats[(b*NG + g)*2 + 1];
    float ga = gn_g[c] * rs;
    float be = gn_b[c] - mu * ga;
    float4 hv = ((const float4*)g_h)[idx4];
    float4 xv = ((const float4*)x)[idx4];
    float4 r;
    r.x = gelu_res(hv.x, xv.x, ga, be);
    r.y = gelu_res(hv.y, xv.y, ga, be);
    r.z = gelu_res(hv.z, xv.z, ga, be);
    r.w = gelu_res(hv.w, xv.w, ga, be);
    ((float4*)out)[idx4] = r;
}

extern "C" void kernel_launch(void* const* d_in, const int* in_sizes, int n_in,
                              void* d_out, int out_size) {
    const float* x        = (const float*)d_in[0];
    const float* t_emb    = (const float*)d_in[1];
    const float* cond_emb = (const float*)d_in[2];
    const float* w_real   = (const float*)d_in[3];
    const float* w_imag   = (const float*)d_in[4];
    const float* pw_w     = (const float*)d_in[5];
    const float* pw_b     = (const float*)d_in[6];
    const float* tp_w     = (const float*)d_in[7];
    const float* tp_b     = (const float*)d_in[8];
    const float* cp_w     = (const float*)d_in[9];
    const float* cp_b     = (const float*)d_in[10];
    const float* gn_g     = (const float*)d_in[11];
    const float* gn_b     = (const float*)d_in[12];
    float* out = (float*)d_out;

    static int smem_set = 0;
    if (!smem_set) {
        cudaFuncSetAttribute(kF_mma, cudaFuncAttributeMaxDynamicSharedMemorySize, 73728);
        cudaFuncSetAttribute(kA_mma, cudaFuncAttributeMaxDynamicSharedMemorySize, 71680);
        cudaFuncSetAttribute(kB_pack, cudaFuncAttributeMaxDynamicSharedMemorySize, 98304);
        cudaFuncSetAttribute(kC_mix6, cudaFuncAttributeMaxDynamicSharedMemorySize, 49152);
        cudaFuncSetAttribute(kDE_fused, cudaFuncAttributeMaxDynamicSharedMemorySize, 76800);
        smem_set = 1;
    }

    k0_prep<<<BB + 1, 256>>>(t_emb, cond_emb, tp_w, tp_b, cp_w, cp_b);
    kA_mma<<<4096, 256, 71680>>>(x);
    kB_pack<<<2048, 256, 98304>>>();
    kC_mix6<<<512, 256, 49152>>>(w_real, w_imag);
    kDE_fused<<<4096, 256, 76800>>>();
    kF_mma<<<4096, 256, 73728>>>(x, pw_w, pw_b);
    kG_stats<<<1, 256>>>();
    kH_final<<<65536, 256>>>(x, gn_g, gn_b, out);
}

// round 9
// speedup vs baseline: 2.0443x; 1.0179x over previous
#include <cuda_runtime.h>
#include <cstdint>
#include <math.h>

#define BB 16
#define CC 256
#define HH 128
#define WW 128
#define HW 16384
#define MM 32
#define NMODE 1024
#define TD 512
#define CD 512
#define NG 8
#define EPSV 1e-5f

typedef unsigned long long u64;

// ---------------- persistent scratch ----------------
__device__ float2 g_A[(size_t)BB*CC*HH*MM];      // kA out; dead after kB; reused as kC half-1 output
__device__ float2 g_Smode[(size_t)BB*CC*NMODE];  // SoA per kx: 64 floats = 16 groups (r,r,i,i)
__device__ float2 g_Omode[(size_t)BB*CC*NMODE];  // kC half-0 output (SoA per kx: 32r + 32i)
__device__ float  g_h[(size_t)BB*CC*HW];
__device__ float  g_tvec[BB*CC];
__device__ float  g_scale[BB*CC];
__device__ float  g_shift[BB*CC];
__device__ float  g_stats[BB*NG*2];
__device__ float2 g_tabJK[HH*MM];
__device__ float2 g_tabKJ[MM*HH];

// ---------------- helpers ----------------
__device__ __forceinline__ uint32_t smem_u32(const void* p) {
    return (uint32_t)__cvta_generic_to_shared(p);
}
__device__ __forceinline__ void cpasync16(uint32_t dst, const void* src) {
    asm volatile("cp.async.ca.shared.global [%0], [%1], 16;" :: "r"(dst), "l"(src));
}
__device__ __forceinline__ void cpcommit() { asm volatile("cp.async.commit_group;"); }
template<int N>
__device__ __forceinline__ void cpwait() { asm volatile("cp.async.wait_group %0;" :: "n"(N)); }
__device__ __forceinline__ uint32_t f2tf(float v) {
    uint32_t r;
    asm("cvt.rna.tf32.f32 %0, %1;" : "=r"(r) : "f"(v));
    return r;
}
__device__ __forceinline__ void mma_tf32(float* d, const uint32_t* a, const uint32_t* b) {
    asm volatile("mma.sync.aligned.m16n8k8.row.col.f32.tf32.tf32.f32 "
                 "{%0,%1,%2,%3}, {%4,%5,%6,%7}, {%8,%9}, {%0,%1,%2,%3};"
                 : "+f"(d[0]), "+f"(d[1]), "+f"(d[2]), "+f"(d[3])
                 : "r"(a[0]), "r"(a[1]), "r"(a[2]), "r"(a[3]), "r"(b[0]), "r"(b[1]));
}
__device__ __forceinline__ u64 pack2(float x, float y) {
    u64 r; asm("mov.b64 %0, {%1, %2};" : "=l"(r) : "f"(x), "f"(y)); return r;
}
__device__ __forceinline__ u64 fma2(u64 a, u64 b, u64 c) {
    u64 d; asm("fma.rn.f32x2 %0, %1, %2, %3;" : "=l"(d) : "l"(a), "l"(b), "l"(c)); return d;
}
__device__ __forceinline__ u64 neg2(u64 a) { return a ^ 0x8000000080000000ULL; }
__device__ __forceinline__ float2 unpack2(u64 a) {
    float2 v; asm("mov.b64 {%0, %1}, %2;" : "=f"(v.x), "=f"(v.y) : "l"(a)); return v;
}

// ---------------- K0 ----------------
__global__ void k0_prep(const float* __restrict__ t_emb, const float* __restrict__ cond_emb,
                        const float* __restrict__ tp_w, const float* __restrict__ tp_b,
                        const float* __restrict__ cp_w, const float* __restrict__ cp_b) {
    int t = threadIdx.x;
    if (blockIdx.x == BB) {
        for (int e = t; e < HH*MM; e += 256) {
            int j = e >> 5, k = e & 31;
            float ang = (float)((j * k) & 127) * 0.049087385212340517f;
            float s, c; sincosf(ang, &s, &c);
            g_tabJK[j*MM + k] = make_float2(c, s);
            g_tabKJ[k*HH + j] = make_float2(c, s);
        }
        if (t < BB*NG*2) g_stats[t] = 0.f;
        return;
    }
    int b = blockIdx.x;
    __shared__ float st[TD];
    __shared__ float sc[CD];
    for (int e = t; e < TD; e += 256) { float v = t_emb[b*TD + e];   st[e] = v / (1.f + expf(-v)); }
    for (int e = t; e < CD; e += 256) { float v = cond_emb[b*CD + e]; sc[e] = v / (1.f + expf(-v)); }
    __syncthreads();
    int c = t;
    float tv = tp_b[c], s1 = cp_b[c], s2 = cp_b[c + CC];
    const float* tw = tp_w + (size_t)c*TD;
    const float* c1 = cp_w + (size_t)c*CD;
    const float* c2 = cp_w + (size_t)(c + CC)*CD;
    for (int d = 0; d < TD; d++) tv = fmaf(st[d], tw[d], tv);
    for (int d = 0; d < CD; d++) { s1 = fmaf(sc[d], c1[d], s1); s2 = fmaf(sc[d], c2[d], s2); }
    g_tvec[b*CC + c] = tv;
    g_scale[b*CC + c] = s1;
    g_shift[b*CC + c] = s2;
}

// ---------------- kA: forward ky-DFT as tf32 GEMM ----------------
#define TSA_(k,n)      sdyn[(k)*68 + (n)]
#define XSA_(st,r,k)   sdyn[8704 + (st)*4608 + (r)*36 + (k)]

__global__ void __launch_bounds__(256, 2) kA_mma(const float* __restrict__ x) {
    extern __shared__ float sdyn[];
    int t = threadIdx.x, lane = t & 31, warp = t >> 5;
    int wm = warp >> 1, wn = warp & 1;
    int R0 = blockIdx.x * 128;

    for (int e = t; e < HH*MM; e += 256) {
        int m = e >> 5, ky = e & 31;
        float2 cs = g_tabJK[e];
        TSA_(m, 2*ky)     = cs.x;
        TSA_(m, 2*ky + 1) = -cs.y;
    }
    #pragma unroll
    for (int q = 0; q < 4; q++) {
        int idx = t + 256*q;
        int row = idx >> 3, c4 = idx & 7;
        cpasync16(smem_u32(&XSA_(0, row, c4*4)), x + (size_t)(R0 + row)*128 + c4*4);
    }
    cpcommit();

    float acc[2][4][4];
    #pragma unroll
    for (int mf = 0; mf < 2; mf++)
        #pragma unroll
        for (int nf = 0; nf < 4; nf++)
            #pragma unroll
            for (int e = 0; e < 4; e++) acc[mf][nf][e] = 0.f;

    for (int kc = 0; kc < 4; kc++) {
        if (kc + 1 < 4) {
            int k0 = (kc + 1) * 32, st2 = (kc + 1) & 1;
            #pragma unroll
            for (int q = 0; q < 4; q++) {
                int idx = t + 256*q;
                int row = idx >> 3, c4 = idx & 7;
                cpasync16(smem_u32(&XSA_(st2, row, c4*4)), x + (size_t)(R0 + row)*128 + k0 + c4*4);
            }
            cpcommit();
            cpwait<1>();
        } else {
            cpwait<0>();
        }
        __syncthreads();
        int st = kc & 1;
        #pragma unroll
        for (int k8 = 0; k8 < 4; k8++) {
            uint32_t a[2][4], b[4][2];
            int arow = wm*32 + (lane >> 2);
            int acol = (lane & 3) + k8*8;
            #pragma unroll
            for (int mf = 0; mf < 2; mf++) {
                int r = arow + mf*16;
                a[mf][0] = f2tf(XSA_(st, r,     acol));
                a[mf][1] = f2tf(XSA_(st, r + 8, acol));
                a[mf][2] = f2tf(XSA_(st, r,     acol + 4));
                a[mf][3] = f2tf(XSA_(st, r + 8, acol + 4));
            }
            int kg = kc*32 + k8*8 + (lane & 3);
            int bn0 = wn*32 + (lane >> 2);
            #pragma unroll
            for (int nf = 0; nf < 4; nf++) {
                b[nf][0] = f2tf(TSA_(kg,     bn0 + nf*8));
                b[nf][1] = f2tf(TSA_(kg + 4, bn0 + nf*8));
            }
            #pragma unroll
            for (int mf = 0; mf < 2; mf++)
                #pragma unroll
                for (int nf = 0; nf < 4; nf++)
                    mma_tf32(acc[mf][nf], a[mf], b[nf]);
        }
        __syncthreads();
    }
    float* Ao = (float*)g_A;
    #pragma unroll
    for (int mf = 0; mf < 2; mf++) {
        int r = R0 + wm*32 + mf*16 + (lane >> 2);
        #pragma unroll
        for (int nf = 0; nf < 4; nf++) {
            int col = wn*32 + nf*8 + 2*(lane & 3);
            *(float2*)&Ao[(size_t)r*64 + col]       = make_float2(acc[mf][nf][0], acc[mf][nf][1]);
            *(float2*)&Ao[(size_t)(r + 8)*64 + col] = make_float2(acc[mf][nf][2], acc[mf][nf][3]);
        }
    }
}

// ---------------- kB: forward DFT along h, packed f32x2; rrii-group output ----------------
#define TCB_(n,kx)    dynB[(n)*32 + (kx)]
#define TSB_(n,kx)    dynB[4096 + (n)*32 + (kx)]
#define SAB_(sl,n,c)  dynB[8192 + (sl)*8192 + (n)*64 + (c)]

__global__ void __launch_bounds__(256, 2) kB_pack() {
    extern __shared__ float dynB[];
    int t = threadIdx.x;
    int bc0 = blockIdx.x * 2;
    for (int e = t; e < 4096; e += 256) {
        float2 cs = g_tabJK[e];       // e = n*32 + kx
        TCB_(e >> 5, e & 31) = cs.x;
        TSB_(e >> 5, e & 31) = cs.y;
    }
    {
        const float4* src = (const float4*)((const float*)g_A + (size_t)bc0*8192);
        float4* dst = (float4*)&dynB[8192];
        #pragma unroll
        for (int q = 0; q < 16; q++) dst[t + 256*q] = src[t + 256*q];
    }
    __syncthreads();

    int sl = t >> 7, u = t & 127;
    int ky = u & 31, grp = u >> 5;
    u64 Srp[4], Sip[4];
    #pragma unroll
    for (int j = 0; j < 4; j++) { Srp[j] = 0ULL; Sip[j] = 0ULL; }

    for (int n = 0; n < HH; n++) {
        float2 a = *(float2*)&SAB_(sl, n, 2*ky);
        u64 arr = pack2(a.x, a.x);
        u64 aii = pack2(a.y, a.y);
        u64 nar = pack2(-a.x, -a.x);
        #pragma unroll
        for (int j = 0; j < 4; j++) {
            int kxp = grp*4 + j;
            u64 cp = *(u64*)&TCB_(n, 2*kxp);
            u64 sp = *(u64*)&TSB_(n, 2*kxp);
            Srp[j] = fma2(arr, cp, fma2(aii, sp, Srp[j]));
            Sip[j] = fma2(aii, cp, fma2(nar, sp, Sip[j]));
        }
    }
    const float scl = 1.f/128.f;
    float* So = (float*)g_Smode + (size_t)(bc0 + sl)*2048;
    int off = (ky >> 1)*4 + (ky & 1);   // rrii group layout
    #pragma unroll
    for (int j = 0; j < 4; j++) {
        int kxp = grp*4 + j;
        float2 r = unpack2(Srp[j]);
        float2 im = unpack2(Sip[j]);
        So[(2*kxp)*64 + off]         = r.x*scl;
        So[(2*kxp + 1)*64 + off]     = r.y*scl;
        So[(2*kxp)*64 + off + 2]     = im.x*scl;
        So[(2*kxp + 1)*64 + off + 2] = im.y*scl;
    }
}

// ---------------- kC: channel mix, split-K (2 halves of i), 6-stage pipeline ----------------
#define SS6(st,b,f)    sdyn[(st) + (b)*64 + (f)]
#define WS6(st,h,o,f)  sdyn[6144 + (st) + (h)*512 + (o)*32 + (f)]

__global__ void __launch_bounds__(256, 2) kC_mix6(const float* __restrict__ w_real,
                                                  const float* __restrict__ w_imag) {
    extern __shared__ float sdyn[];
    int t = threadIdx.x;
    int ih = blockIdx.x >> 9;            // channel half: 0 or 1
    int kx = (blockIdx.x >> 4) & 31;
    int o0 = (blockIdx.x & 15) << 4;
    int i0 = ih << 7;                    // 0 or 128
    const int NI = 128;

    int sb = t >> 4, sf = t & 15;                       // S copy role
    const float* wsrc = (t < 128) ? w_real : w_imag;    // W copy role
    int whalf = t >> 7, wo = (t >> 3) & 15, wf = t & 7;

    int kyp = t & 15, bq = (t >> 4) & 3, oq = t >> 6;

    u64 ar[4][4], ai[4][4];
    #pragma unroll
    for (int b4 = 0; b4 < 4; b4++)
        #pragma unroll
        for (int o4 = 0; o4 < 4; o4++) { ar[b4][o4] = 0ULL; ai[b4][o4] = 0ULL; }

    const float* sPtr = (const float*)g_Smode + (size_t)(sb*CC + i0)*2048 + kx*64 + sf*4;
    const float* wPtr = wsrc + ((size_t)(i0*CC + o0 + wo) << 10) + (kx << 5) + wf*4;
    uint32_t sDst = smem_u32(&SS6(0, sb, sf*4));
    uint32_t wDst = smem_u32(&WS6(0, whalf, wo, wf*4));

    #pragma unroll
    for (int i = 0; i < 5; i++) {
        cpasync16(sDst + i*4096, sPtr);  sPtr += 2048;
        cpasync16(wDst + i*4096, wPtr);  wPtr += (size_t)CC << 10;
        cpcommit();
    }

    int stc = 0;
    int stp = 5*1024;
    uint32_t sPD = sDst + 5*4096, wPD = wDst + 5*4096;

    for (int i = 0; i < NI; i++) {
        cpwait<4>();
        __syncthreads();
        if (i + 5 < NI) {
            cpasync16(sPD, sPtr);  sPtr += 2048;
            cpasync16(wPD, wPtr);  wPtr += (size_t)CC << 10;
        }
        cpcommit();
        sPD += 4096; wPD += 4096;
        if (stp == 5*1024) { sPD -= 6*4096; wPD -= 6*4096; stp = 0; } else stp += 1024;

        int st = stc;
        u64 sx[4], sy[4], nsy[4];
        #pragma unroll
        for (int b4 = 0; b4 < 4; b4++) {
            int b = 4*b4 + bq;
            sx[b4]  = *(u64*)&SS6(st, b, 4*kyp);
            sy[b4]  = *(u64*)&SS6(st, b, 4*kyp + 2);
            nsy[b4] = neg2(sy[b4]);
        }
        #pragma unroll
        for (int o4 = 0; o4 < 4; o4++) {
            int ow = 4*o4 + oq;
            u64 wr = *(u64*)&WS6(st, 0, ow, 2*kyp);
            u64 wi = *(u64*)&WS6(st, 1, ow, 2*kyp);
            #pragma unroll
            for (int b4 = 0; b4 < 4; b4++) {
                ar[b4][o4] = fma2(sx[b4], wr, fma2(nsy[b4], wi, ar[b4][o4]));
                ai[b4][o4] = fma2(sx[b4], wi, fma2(sy[b4],  wr, ai[b4][o4]));
            }
        }
        stc = (stc == 5*1024) ? 0 : stc + 1024;
    }
    float* OmF = ih ? (float*)g_A : (float*)g_Omode;
    #pragma unroll
    for (int b4 = 0; b4 < 4; b4++) {
        int b = 4*b4 + bq;
        #pragma unroll
        for (int o4 = 0; o4 < 4; o4++) {
            int o = o0 + 4*o4 + oq;
            float* dst = OmF + (size_t)(b*CC + o)*2048 + kx*64;
            *(float2*)&dst[2*kyp]      = unpack2(ar[b4][o4]);
            *(float2*)&dst[32 + 2*kyp] = unpack2(ai[b4][o4]);
        }
    }
}

// ---------------- kDE: fused inverse kx-DFT + inverse C2R ky (tf32 mma); merges split-K halves ----------------
#define GSE_(r,k)   sdyn[(r)*68 + (k)]
#define USE_(k,n)   sdyn[8704 + (k)*132 + (n)]
#define SOD_(kx,f)  sdyn[17152 + (kx)*64 + (f)]

__global__ void __launch_bounds__(256, 2) kDE_fused() {
    extern __shared__ float sdyn[];
    int t = threadIdx.x, lane = t & 31, warp = t >> 5;
    int wm = warp >> 1, wn = warp & 1;
    int bo = blockIdx.x;

    for (int e = t; e < MM*HH; e += 256) {
        int ky = e >> 7, m = e & 127;
        float2 cs = g_tabKJ[e];
        USE_(2*ky,     m) = cs.x;
        USE_(2*ky + 1, m) = -cs.y;
    }
    // load O modes: sum of the two split-K halves
    {
        const float4* s1 = (const float4*)((const float*)g_Omode + (size_t)bo*2048);
        const float4* s2 = (const float4*)((const float*)g_A + (size_t)bo*2048);
        #pragma unroll
        for (int q = 0; q < 2; q++) {
            float4 a = s1[t + 256*q], b = s2[t + 256*q];
            ((float4*)&SOD_(0,0))[t + 256*q] =
                make_float4(a.x + b.x, a.y + b.y, a.z + b.z, a.w + b.w);
        }
    }
    __syncthreads();

    // ---- phase 1: kD (kx -> n), packed f32x2, writes GSE ----
    {
        int ky = t & 31, npg = t >> 5;
        u64 Grp[8], Gip[8];
        #pragma unroll
        for (int j = 0; j < 8; j++) { Grp[j] = 0ULL; Gip[j] = 0ULL; }
        for (int kx = 0; kx < MM; kx++) {
            float Or = SOD_(kx, ky), Oi = SOD_(kx, 32 + ky);
            u64 Orr  = pack2(Or, Or);
            u64 Oii  = pack2(Oi, Oi);
            u64 nOrr = pack2(-Or, -Or);
            #pragma unroll
            for (int j = 0; j < 8; j++) {
                int n0 = npg*16 + 2*j;
                u64 cp  = *(u64*)&USE_(2*kx,     n0);
                u64 spn = *(u64*)&USE_(2*kx + 1, n0);
                Grp[j] = fma2(Orr, cp, fma2(Oii, spn, Grp[j]));
                Gip[j] = fma2(nOrr, spn, fma2(Oii, cp, Gip[j]));
            }
        }
        float fac = (ky == 0 ? 1.f : 2.f) * (1.f/128.f);
        #pragma unroll
        for (int j = 0; j < 8; j++) {
            int n0 = npg*16 + 2*j;
            float2 gr = unpack2(Grp[j]);
            float2 gi = unpack2(Gip[j]);
            *(float2*)&GSE_(n0,     2*ky) = make_float2(gr.x*fac, gi.x*fac);
            *(float2*)&GSE_(n0 + 1, 2*ky) = make_float2(gr.y*fac, gi.y*fac);
        }
    }
    __syncthreads();

    // ---- phase 2: kE tf32 mma ----
    float acc[2][8][4];
    #pragma unroll
    for (int mf = 0; mf < 2; mf++)
        #pragma unroll
        for (int nf = 0; nf < 8; nf++)
            #pragma unroll
            for (int e = 0; e < 4; e++) acc[mf][nf][e] = 0.f;

    #pragma unroll
    for (int k8 = 0; k8 < 8; k8++) {
        uint32_t a[2][4], b[8][2];
        int arow = wm*32 + (lane >> 2);
        int acol = (lane & 3) + k8*8;
        #pragma unroll
        for (int mf = 0; mf < 2; mf++) {
            int r = arow + mf*16;
            a[mf][0] = f2tf(GSE_(r,     acol));
            a[mf][1] = f2tf(GSE_(r + 8, acol));
            a[mf][2] = f2tf(GSE_(r,     acol + 4));
            a[mf][3] = f2tf(GSE_(r + 8, acol + 4));
        }
        int kg = k8*8 + (lane & 3);
        int bn0 = wn*64 + (lane >> 2);
        #pragma unroll
        for (int nf = 0; nf < 8; nf++) {
            b[nf][0] = f2tf(USE_(kg,     bn0 + nf*8));
            b[nf][1] = f2tf(USE_(kg + 4, bn0 + nf*8));
        }
        #pragma unroll
        for (int mf = 0; mf < 2; mf++)
            #pragma unroll
            for (int nf = 0; nf < 8; nf++)
                mma_tf32(acc[mf][nf], a[mf], b[nf]);
    }

    #pragma unroll
    for (int mf = 0; mf < 2; mf++) {
        int r = bo*128 + wm*32 + mf*16 + (lane >> 2);
        #pragma unroll
        for (int nf = 0; nf < 8; nf++) {
            int col = wn*64 + nf*8 + 2*(lane & 3);
            *(float2*)&g_h[(size_t)r*128 + col]       = make_float2(acc[mf][nf][0], acc[mf][nf][1]);
            *(float2*)&g_h[(size_t)(r + 8)*128 + col] = make_float2(acc[mf][nf][2], acc[mf][nf][3]);
        }
    }
}

// ---------------- kF: pointwise GEMM via tf32 mma + fused epilogue + GN stats ----------------
#define ASM_(st,r,c) sdyn[(st)*4608 + (r)*36 + (c)]
#define BSM_(st,k,n) sdyn[9216 + (st)*4352 + (k)*136 + (n)]

__global__ void __launch_bounds__(256, 2) kF_mma(const float* __restrict__ x,
                                                 const float* __restrict__ pw_w,
                                                 const float* __restrict__ pw_b) {
    extern __shared__ float sdyn[];
    int t = threadIdx.x;
    int lane = t & 31, warp = t >> 5;
    int wm = warp >> 1, wn = warp & 1;
    int bi = blockIdx.x;
    int bb = bi >> 8;
    int ot = (bi >> 7) & 1, hwt = bi & 127;
    int o0 = ot * 128, hw0 = hwt * 128;

    float acc[2][8][4];
    #pragma unroll
    for (int mf = 0; mf < 2; mf++)
        #pragma unroll
        for (int nf = 0; nf < 8; nf++)
            #pragma unroll
            for (int e = 0; e < 4; e++) acc[mf][nf][e] = 0.f;

    {
        int i0 = 0;
        #pragma unroll
        for (int q = 0; q < 4; q++) {
            int idx = t + 256*q;
            int row = idx >> 3, c4 = idx & 7;
            cpasync16(smem_u32(&ASM_(0, row, c4*4)), pw_w + (size_t)(o0 + row)*CC + i0 + c4*4);
        }
        #pragma unroll
        for (int q = 0; q < 4; q++) {
            int idx = t + 256*q;
            int row = idx >> 5, c4 = idx & 31;
            cpasync16(smem_u32(&BSM_(0, row, c4*4)),
                      x + (((size_t)(bb*CC + i0 + row)) << 14) + hw0 + c4*4);
        }
        cpcommit();
    }

    for (int kc = 0; kc < 8; kc++) {
        if (kc + 1 < 8) {
            int i0 = (kc + 1) * 32, st2 = (kc + 1) & 1;
            #pragma unroll
            for (int q = 0; q < 4; q++) {
                int idx = t + 256*q;
                int row = idx >> 3, c4 = idx & 7;
                cpasync16(smem_u32(&ASM_(st2, row, c4*4)), pw_w + (size_t)(o0 + row)*CC + i0 + c4*4);
            }
            #pragma unroll
            for (int q = 0; q < 4; q++) {
                int idx = t + 256*q;
                int row = idx >> 5, c4 = idx & 31;
                cpasync16(smem_u32(&BSM_(st2, row, c4*4)),
                          x + (((size_t)(bb*CC + i0 + row)) << 14) + hw0 + c4*4);
            }
            cpcommit();
            cpwait<1>();
        } else {
            cpwait<0>();
        }
        __syncthreads();
        int st = kc & 1;
        #pragma unroll
        for (int k8 = 0; k8 < 4; k8++) {
            uint32_t a[2][4], b[8][2];
            int arow = wm*32 + (lane >> 2);
            int acol = (lane & 3) + k8*8;
            #pragma unroll
            for (int mf = 0; mf < 2; mf++) {
                int r = arow + mf*16;
                a[mf][0] = f2tf(ASM_(st, r,     acol));
                a[mf][1] = f2tf(ASM_(st, r + 8, acol));
                a[mf][2] = f2tf(ASM_(st, r,     acol + 4));
                a[mf][3] = f2tf(ASM_(st, r + 8, acol + 4));
            }
            int bk = (lane & 3) + k8*8;
            int bn0 = wn*64 + (lane >> 2);
            #pragma unroll
            for (int nf = 0; nf < 8; nf++) {
                b[nf][0] = f2tf(BSM_(st, bk,     bn0 + nf*8));
                b[nf][1] = f2tf(BSM_(st, bk + 4, bn0 + nf*8));
            }
            #pragma unroll
            for (int mf = 0; mf < 2; mf++)
                #pragma unroll
                for (int nf = 0; nf < 8; nf++)
                    mma_tf32(acc[mf][nf], a[mf], b[nf]);
        }
        __syncthreads();
    }

    float lsum = 0.f, lsum2 = 0.f;
    #pragma unroll
    for (int mf = 0; mf < 2; mf++) {
        int rbase = o0 + wm*32 + mf*16 + (lane >> 2);
        float addb[2], scl[2], shf[2];
        #pragma unroll
        for (int h = 0; h < 2; h++) {
            int o = rbase + 8*h;
            addb[h] = pw_b[o] + g_tvec[bb*CC + o];
            scl[h]  = 1.f + g_scale[bb*CC + o];
            shf[h]  = g_shift[bb*CC + o];
        }
        #pragma unroll
        for (int nf = 0; nf < 8; nf++) {
            int col = hw0 + wn*64 + nf*8 + 2*(lane & 3);
            #pragma unroll
            for (int h = 0; h < 2; h++) {
                size_t idx = (((size_t)(bb*CC + rbase + 8*h)) << 14) + col;
                float2 hv = *(float2*)&g_h[idx];
                float v0 = (acc[mf][nf][2*h]     + hv.x + addb[h]) * scl[h] + shf[h];
                float v1 = (acc[mf][nf][2*h + 1] + hv.y + addb[h]) * scl[h] + shf[h];
                *(float2*)&g_h[idx] = make_float2(v0, v1);
                lsum  += v0 + v1;
                lsum2 += v0*v0 + v1*v1;
            }
        }
    }
    #pragma unroll
    for (int off = 16; off; off >>= 1) {
        lsum  += __shfl_xor_sync(0xffffffffu, lsum, off);
        lsum2 += __shfl_xor_sync(0xffffffffu, lsum2, off);
    }
    if (lane == 0) {
        int g = (o0 + wm*32) >> 5;
        atomicAdd(&g_stats[(bb*NG + g)*2],     lsum);
        atomicAdd(&g_stats[(bb*NG + g)*2 + 1], lsum2);
    }
}

// ---------------- kG ----------------
__global__ void kG_stats() {
    int t = threadIdx.x;
    if (t < BB*NG) {
        float s = g_stats[t*2], s2 = g_stats[t*2 + 1];
        const float inv = 1.f / 524288.f;
        float mu = s * inv;
        float var = s2 * inv - mu*mu;
        g_stats[t*2]     = mu;
        g_stats[t*2 + 1] = rsqrtf(var + EPSV);
    }
}

// ---------------- kH ----------------
__device__ __forceinline__ float gelu_res(float h, float xr, float ga, float be) {
    float hn = fmaf(h, ga, be);
    return xr + 0.5f*hn*(1.f + erff(hn*0.70710678118654752f));
}

__global__ void __launch_bounds__(256) kH_final(const float* __restrict__ x,
                                                const float* __restrict__ gn_g,
                                                const float* __restrict__ gn_b,
                                                float* __restrict__ out) {
    int idx4 = blockIdx.x*256 + threadIdx.x;
    int base = idx4 << 2;
    int c = (base >> 14) & 255;
    int b = base >> 22;
    int g = c >> 5;
    float mu = g_stats[(b*NG + g)*2];
    float rs = g_stats[(b*NG + g)*2 + 1];
    float ga = gn_g[c] * rs;
    float be = gn_b[c] - mu * ga;
    float4 hv = ((const float4*)g_h)[idx4];
    float4 xv = ((const float4*)x)[idx4];
    float4 r;
    r.x = gelu_res(hv.x, xv.x, ga, be);
    r.y = gelu_res(hv.y, xv.y, ga, be);
    r.z = gelu_res(hv.z, xv.z, ga, be);
    r.w = gelu_res(hv.w, xv.w, ga, be);
    ((float4*)out)[idx4] = r;
}

extern "C" void kernel_launch(void* const* d_in, const int* in_sizes, int n_in,
                              void* d_out, int out_size) {
    const float* x        = (const float*)d_in[0];
    const float* t_emb    = (const float*)d_in[1];
    const float* cond_emb = (const float*)d_in[2];
    const float* w_real   = (const float*)d_in[3];
    const float* w_imag   = (const float*)d_in[4];
    const float* pw_w     = (const float*)d_in[5];
    const float* pw_b     = (const float*)d_in[6];
    const float* tp_w     = (const float*)d_in[7];
    const float* tp_b     = (const float*)d_in[8];
    const float* cp_w     = (const float*)d_in[9];
    const float* cp_b     = (const float*)d_in[10];
    const float* gn_g     = (const float*)d_in[11];
    const float* gn_b     = (const float*)d_in[12];
    float* out = (float*)d_out;

    static int smem_set = 0;
    if (!smem_set) {
        cudaFuncSetAttribute(kF_mma, cudaFuncAttributeMaxDynamicSharedMemorySize, 73728);
        cudaFuncSetAttribute(kA_mma, cudaFuncAttributeMaxDynamicSharedMemorySize, 71680);
        cudaFuncSetAttribute(kB_pack, cudaFuncAttributeMaxDynamicSharedMemorySize, 98304);
        cudaFuncSetAttribute(kC_mix6, cudaFuncAttributeMaxDynamicSharedMemorySize, 49152);
        cudaFuncSetAttribute(kDE_fused, cudaFuncAttributeMaxDynamicSharedMemorySize, 76800);
        smem_set = 1;
    }

    k0_prep<<<BB + 1, 256>>>(t_emb, cond_emb, tp_w, tp_b, cp_w, cp_b);
    kA_mma<<<4096, 256, 71680>>>(x);
    kB_pack<<<2048, 256, 98304>>>();
    kC_mix6<<<1024, 256, 49152>>>(w_real, w_imag);
    kDE_fused<<<4096, 256, 76800>>>();
    kF_mma<<<4096, 256, 73728>>>(x, pw_w, pw_b);
    kG_stats<<<1, 256>>>();
    kH_final<<<65536, 256>>>(x, gn_g, gn_b, out);
}